// round 7
// baseline (speedup 1.0000x reference)
#include <cuda_runtime.h>
#include <cuda_bf16.h>
#include <math.h>
#include <mma.h>

using namespace nvcuda;

// ---------------------------------------------------------------------------
// ScaffoldGAN JTNN GRU + discriminator. R7: 3xTF32 WMMA with hi/lo split
// hoisted to the smem-load stage (R6 split per fragment-load -> ALU-bound).
//   * wmma_gemm: 128x128x16, 4 smem tiles (Ahi/Alo/Whi/Wlo), single-buffered
//     with register prefetch; inner loop = pure fragment loads + 3x MMA.
//   * rel_err with this scheme measured 5.0e-5 in R6 (same math).
// ---------------------------------------------------------------------------

#define HH     450
#define NNODES 4000
#define NMESS  6000
#define KNB    6
#define BB     256
#define DHH    450
#define MAXDEPTH 15
#define MROWS  6016

#define LDX   512
#define LDZU  1024
#define LDPRE 1536

// ---------------- device scratch ------------------
__device__ float g_fe[NNODES * HH];
__device__ float g_x[MROWS * LDX];
__device__ float g_xzrh[MROWS * LDPRE];
__device__ float g_h[MROWS * LDX];
__device__ float g_hZU[MROWS * LDZU];
__device__ float g_sumh[MROWS * LDX];
__device__ float g_z[MROWS * LDX];
__device__ float g_sumgh[MROWS * LDX];
__device__ float g_preh[MROWS * LDX];
__device__ float g_Wpre[1350 * LDX];
__device__ float g_Wstep[900 * LDX];
__device__ float g_Whh[HH * LDX];
__device__ float g_bias[1536];
__device__ float g_rv[BB * 2 * HH];
__device__ float g_d1[BB * DHH];
__device__ float g_d2[BB * DHH];

// ---------------------------- small kernels --------------------------------
__global__ void zero_kernel(float* p, int n) {
    int i = blockIdx.x * blockDim.x + threadIdx.x;
    if (i < n) p[i] = 0.f;
}

__global__ void pack_kernel(const float* __restrict__ W_z_w,
                            const float* __restrict__ W_h_w,
                            const float* __restrict__ W_r_w,
                            const float* __restrict__ U_r_w,
                            const float* __restrict__ W_z_b,
                            const float* __restrict__ W_h_b,
                            const float* __restrict__ U_r_b,
                            float* __restrict__ Wpre,
                            float* __restrict__ Wstep,
                            float* __restrict__ Whh,
                            float* __restrict__ bias) {
    int i = blockIdx.x * blockDim.x + threadIdx.x;
    const int NPRE  = 1350 * HH;
    const int NSTEP = 900 * HH;
    const int NWHH  = HH * HH;
    if (i < NPRE) {
        int n = i / HH, k = i - n * HH;
        float v;
        if (n < HH)            v = W_z_w[n * 2 * HH + k];
        else if (n < 2 * HH)   v = W_h_w[(n - HH) * 2 * HH + k];
        else                   v = W_r_w[(n - 2 * HH) * HH + k];
        Wpre[n * LDX + k] = v;
    } else if (i < NPRE + NSTEP) {
        int j = i - NPRE;
        int n = j / HH, k = j - n * HH;
        float v = (n < HH) ? W_z_w[n * 2 * HH + HH + k]
                           : U_r_w[(n - HH) * HH + k];
        Wstep[n * LDX + k] = v;
    } else if (i < NPRE + NSTEP + NWHH) {
        int j = i - NPRE - NSTEP;
        int n = j / HH, k = j - n * HH;
        Whh[n * LDX + k] = W_h_w[n * 2 * HH + HH + k];
    } else if (i < NPRE + NSTEP + NWHH + 1350) {
        int n = i - NPRE - NSTEP - NWHH;
        bias[n] = (n < HH) ? W_z_b[n]
                : (n < 2 * HH) ? W_h_b[n - HH]
                : U_r_b[n - 2 * HH];
    }
}

__global__ void gather_fe_kernel(const float* __restrict__ emb,
                                 const int* __restrict__ fnode,
                                 float* __restrict__ fe) {
    int i = blockIdx.x * blockDim.x + threadIdx.x;
    if (i >= NNODES * HH) return;
    int r = i / HH, c = i - r * HH;
    fe[i] = emb[fnode[r] * HH + c];
}

__global__ void gather_x_kernel(const float* __restrict__ fe,
                                const int* __restrict__ fmess,
                                float* __restrict__ x) {
    int i = blockIdx.x * blockDim.x + threadIdx.x;
    if (i >= NMESS * HH) return;
    int r = i / HH, c = i - r * HH;
    x[r * LDX + c] = fe[fmess[r] * HH + c];
}

__device__ __forceinline__ float2 sigm2(float2 v) {
    return make_float2(1.f / (1.f + __expf(-v.x)), 1.f / (1.f + __expf(-v.y)));
}
__device__ __forceinline__ float2 tanh2(float2 v) {
    return make_float2(tanhf(v.x), tanhf(v.y));
}

#define C2 225

__global__ void step0_kernel(const float* __restrict__ xzrh,
                             const float* __restrict__ bias,
                             float* __restrict__ h,
                             const int* __restrict__ depthp) {
    if (depthp && __ldg(depthp) < 1) return;
    int i = blockIdx.x * blockDim.x + threadIdx.x;
    if (i >= NMESS * C2) return;
    int m = i / C2, c = i - m * C2;
    const float2* xp = (const float2*)xzrh + (size_t)m * (LDPRE / 2);
    const float2* bp = (const float2*)bias;
    float2 xz = xp[c],        bz = bp[c];
    float2 xh = xp[C2 + c],   bh = bp[C2 + c];
    float2 zv = sigm2(make_float2(xz.x + bz.x, xz.y + bz.y));
    float2 ph = tanh2(make_float2(xh.x + bh.x, xh.y + bh.y));
    float2 v = make_float2(zv.x * ph.x, zv.y * ph.y);
    if (m == 0) v = make_float2(0.f, 0.f);
    ((float2*)h)[(size_t)m * (LDX / 2) + c] = v;
}

__global__ void step_gather_kernel(const float* __restrict__ h,
                                   const float* __restrict__ hZU,
                                   const float* __restrict__ xzrh,
                                   const float* __restrict__ bias,
                                   const int* __restrict__ mg,
                                   float* __restrict__ sumh,
                                   float* __restrict__ z,
                                   float* __restrict__ sumgh,
                                   const int* __restrict__ depthp, int step) {
    if (depthp && step >= __ldg(depthp)) return;
    int i = blockIdx.x * blockDim.x + threadIdx.x;
    if (i >= NMESS * C2) return;
    int m = i / C2, c = i - m * C2;
    const float2* xp = (const float2*)xzrh + (size_t)m * (LDPRE / 2);
    const float2* bp = (const float2*)bias;
    float2 xr = xp[2 * C2 + c], br = bp[2 * C2 + c];
    float xr0 = xr.x + br.x, xr1 = xr.y + br.y;
    float2 sh = make_float2(0.f, 0.f);
    float2 sz = make_float2(0.f, 0.f);
    float2 sg = make_float2(0.f, 0.f);
    int idx[KNB];
#pragma unroll
    for (int k = 0; k < KNB; k++) idx[k] = mg[m * KNB + k];
#pragma unroll
    for (int k = 0; k < KNB; k++) {
        int j = idx[k];
        float2 hv = ((const float2*)h)[(size_t)j * (LDX / 2) + c];
        float2 zz = ((const float2*)hZU)[(size_t)j * (LDZU / 2) + c];
        float2 uu = ((const float2*)hZU)[(size_t)j * (LDZU / 2) + C2 + c];
        sh.x += hv.x; sh.y += hv.y;
        sz.x += zz.x; sz.y += zz.y;
        sg.x += hv.x / (1.f + __expf(-(xr0 + uu.x)));
        sg.y += hv.y / (1.f + __expf(-(xr1 + uu.y)));
    }
    size_t o = (size_t)m * (LDX / 2) + c;
    ((float2*)sumh)[o] = sh;
    float2 xz = xp[c], bz = bp[c];
    ((float2*)z)[o] = sigm2(make_float2(sz.x + xz.x + bz.x, sz.y + xz.y + bz.y));
    ((float2*)sumgh)[o] = sg;
}

__global__ void h_update_kernel(const float* __restrict__ preh,
                                const float* __restrict__ xzrh,
                                const float* __restrict__ bias,
                                const float* __restrict__ z,
                                const float* __restrict__ sumh,
                                float* __restrict__ h,
                                const int* __restrict__ depthp, int step) {
    if (depthp && step >= __ldg(depthp)) return;
    int i = blockIdx.x * blockDim.x + threadIdx.x;
    if (i >= NMESS * C2) return;
    int m = i / C2, c = i - m * C2;
    size_t o = (size_t)m * (LDX / 2) + c;
    float2 pv = ((const float2*)preh)[o];
    float2 xh = ((const float2*)xzrh)[(size_t)m * (LDPRE / 2) + C2 + c];
    float2 bh = ((const float2*)bias)[C2 + c];
    float2 ph = tanh2(make_float2(pv.x + xh.x + bh.x, pv.y + xh.y + bh.y));
    float2 zv = ((const float2*)z)[o];
    float2 sh = ((const float2*)sumh)[o];
    float2 v = make_float2((1.f - zv.x) * sh.x + zv.x * ph.x,
                           (1.f - zv.y) * sh.y + zv.y * ph.y);
    if (m == 0) v = make_float2(0.f, 0.f);
    ((float2*)h)[o] = v;
}

__global__ void readout_kernel(const float* __restrict__ fe,
                               const float* __restrict__ h,
                               const int* __restrict__ root,
                               const int* __restrict__ ng,
                               float* __restrict__ rv) {
    int i = blockIdx.x * blockDim.x + threadIdx.x;
    if (i >= BB * HH) return;
    int b = i / HH, c = i - b * HH;
    int node = root[b];
    rv[b * 2 * HH + c] = fe[node * HH + c];
    float s = 0.f;
#pragma unroll
    for (int k = 0; k < KNB; k++)
        s += h[(size_t)ng[node * KNB + k] * LDX + c];
    rv[b * 2 * HH + HH + c] = s;
}

__global__ void score_kernel(const float* __restrict__ h2,
                             const float* __restrict__ w,
                             const float* __restrict__ b3,
                             float* __restrict__ out) {
    int gt = blockIdx.x * blockDim.x + threadIdx.x;
    int warp = gt >> 5, lane = gt & 31;
    if (warp >= BB) return;
    float s = 0.f;
    for (int k = lane; k < DHH; k += 32) s += h2[warp * DHH + k] * w[k];
#pragma unroll
    for (int o = 16; o; o >>= 1) s += __shfl_xor_sync(0xffffffffu, s, o);
    if (lane == 0) out[warp] = s + b3[0];
}

// ----------------------- 3xTF32 compensated WMMA GEMM ----------------------
// hi/lo split done ONCE at smem store; inner loop = frag loads + 3x MMA.
#define WBM 128
#define WBN 128
#define WBK 16
#define KPAD 20

__device__ __forceinline__ float4 ldg4_guard(const float* __restrict__ p,
                                             int row, int gk,
                                             int maxr, int K, int ld) {
    float4 v = make_float4(0.f, 0.f, 0.f, 0.f);
    if (row < maxr) {
        const float* q = p + (size_t)row * ld + gk;
        if (gk + 4 <= K) {
            v = *reinterpret_cast<const float4*>(q);
        } else {
            if (gk     < K) v.x = q[0];
            if (gk + 1 < K) v.y = q[1];
            if (gk + 2 < K) v.z = q[2];
            if (gk + 3 < K) v.w = q[3];
        }
    }
    return v;
}

__device__ __forceinline__ void split4(float4 v, float4& hi, float4& lo) {
    hi.x = wmma::__float_to_tf32(v.x); lo.x = wmma::__float_to_tf32(v.x - hi.x);
    hi.y = wmma::__float_to_tf32(v.y); lo.y = wmma::__float_to_tf32(v.y - hi.y);
    hi.z = wmma::__float_to_tf32(v.z); lo.z = wmma::__float_to_tf32(v.z - hi.z);
    hi.w = wmma::__float_to_tf32(v.w); lo.w = wmma::__float_to_tf32(v.w - hi.w);
}

__global__ __launch_bounds__(256)
void wmma_gemm(const float* __restrict__ A, int lda,
               const float* __restrict__ W, int ldw,
               int M, int N, int K,
               float* __restrict__ C, int ldc,
               const int* __restrict__ depthp, int step) {
    if (depthp && step >= __ldg(depthp)) return;

    __shared__ float Ahi[WBM][KPAD];
    __shared__ float Alo[WBM][KPAD];
    __shared__ float Bhi[WBN][KPAD];
    __shared__ float Blo[WBN][KPAD];

    const int tid = threadIdx.x;
    const int wid = tid >> 5;
    const int wm = wid & 1;       // 2 warps along M (64 rows each)
    const int wn = wid >> 1;      // 4 warps along N (32 cols each)
    const int bm = blockIdx.y * WBM;
    const int bn = blockIdx.x * WBN;

    wmma::fragment<wmma::accumulator, 16, 16, 8, float> acc[4][2];
#pragma unroll
    for (int i = 0; i < 4; i++)
#pragma unroll
        for (int j = 0; j < 2; j++) wmma::fill_fragment(acc[i][j], 0.f);

    int rr[2], kq[2];
#pragma unroll
    for (int t = 0; t < 2; t++) {
        int q = tid + t * 256;
        rr[t] = q >> 2;            // 0..127
        kq[t] = (q & 3) << 2;      // 0,4,8,12
    }

    const int NT = (K + WBK - 1) / WBK;

    // prefetch tile 0 into registers
    float4 ra[2], rw[2];
#pragma unroll
    for (int t = 0; t < 2; t++) {
        ra[t] = ldg4_guard(A, bm + rr[t], kq[t], M, K, lda);
        rw[t] = ldg4_guard(W, bn + rr[t], kq[t], N, K, ldw);
    }

    for (int t0 = 0; t0 < NT; t0++) {
        // store current tile (hi/lo split once per element)
#pragma unroll
        for (int t = 0; t < 2; t++) {
            float4 hi, lo;
            split4(ra[t], hi, lo);
            *reinterpret_cast<float4*>(&Ahi[rr[t]][kq[t]]) = hi;
            *reinterpret_cast<float4*>(&Alo[rr[t]][kq[t]]) = lo;
            split4(rw[t], hi, lo);
            *reinterpret_cast<float4*>(&Bhi[rr[t]][kq[t]]) = hi;
            *reinterpret_cast<float4*>(&Blo[rr[t]][kq[t]]) = lo;
        }
        __syncthreads();

        // prefetch next tile while computing
        if (t0 + 1 < NT) {
            int k0 = (t0 + 1) * WBK;
#pragma unroll
            for (int t = 0; t < 2; t++) {
                ra[t] = ldg4_guard(A, bm + rr[t], k0 + kq[t], M, K, lda);
                rw[t] = ldg4_guard(W, bn + rr[t], k0 + kq[t], N, K, ldw);
            }
        }

#pragma unroll
        for (int kk = 0; kk < WBK; kk += 8) {
            wmma::fragment<wmma::matrix_b, 16, 16, 8, wmma::precision::tf32,
                           wmma::col_major> bhi[2], blo[2];
#pragma unroll
            for (int j = 0; j < 2; j++) {
                wmma::load_matrix_sync(bhi[j], &Bhi[wn * 32 + j * 16][kk], KPAD);
                wmma::load_matrix_sync(blo[j], &Blo[wn * 32 + j * 16][kk], KPAD);
            }
#pragma unroll
            for (int i = 0; i < 4; i++) {
                wmma::fragment<wmma::matrix_a, 16, 16, 8, wmma::precision::tf32,
                               wmma::row_major> ahi, alo;
                wmma::load_matrix_sync(ahi, &Ahi[wm * 64 + i * 16][kk], KPAD);
                wmma::load_matrix_sync(alo, &Alo[wm * 64 + i * 16][kk], KPAD);
#pragma unroll
                for (int j = 0; j < 2; j++) {
                    wmma::mma_sync(acc[i][j], alo, bhi[j], acc[i][j]);
                    wmma::mma_sync(acc[i][j], ahi, blo[j], acc[i][j]);
                    wmma::mma_sync(acc[i][j], ahi, bhi[j], acc[i][j]);
                }
            }
        }
        __syncthreads();
    }

#pragma unroll
    for (int i = 0; i < 4; i++)
#pragma unroll
        for (int j = 0; j < 2; j++) {
            float* cp = C + (size_t)(bm + wm * 64 + i * 16) * ldc
                          + bn + wn * 32 + j * 16;
            wmma::store_matrix_sync(cp, acc[i][j], ldc, wmma::mem_row_major);
        }
}

// ------------------ fp32 SIMT GEMM (discriminator only) --------------------
#define BM 64
#define BN 64
#define BKK 16
#define TMs 4
#define TNs 4

__global__ __launch_bounds__(256)
void disc_gemm(const float* __restrict__ A, int lda,
               const float* __restrict__ W, int ldw,
               int M, int N, int K,
               const float* __restrict__ bias,
               float* __restrict__ C, int ldc) {
    __shared__ float As[BKK][BM];
    __shared__ float Ws[BKK][BN];
    int bm = blockIdx.y * BM, bn = blockIdx.x * BN;
    int tid = threadIdx.x;
    int tr = tid >> 4, tc = tid & 15;
    float acc[TMs][TNs];
#pragma unroll
    for (int i = 0; i < TMs; i++)
#pragma unroll
        for (int j = 0; j < TNs; j++) acc[i][j] = 0.f;
    for (int k0 = 0; k0 < K; k0 += BKK) {
#pragma unroll
        for (int t = 0; t < 4; t++) {
            int l = tid + t * 256;
            int i = l >> 4, j = l & 15;
            int gm = bm + i, gk = k0 + j;
            As[j][i] = (gm < M && gk < K) ? A[(size_t)gm * lda + gk] : 0.f;
        }
#pragma unroll
        for (int t = 0; t < 4; t++) {
            int l = tid + t * 256;
            int i = l >> 4, j = l & 15;
            int gn = bn + i, gk = k0 + j;
            Ws[j][i] = (gn < N && gk < K) ? W[(size_t)gn * ldw + gk] : 0.f;
        }
        __syncthreads();
#pragma unroll
        for (int kk = 0; kk < BKK; kk++) {
            float a[TMs], w[TNs];
#pragma unroll
            for (int i = 0; i < TMs; i++) a[i] = As[kk][tr * TMs + i];
#pragma unroll
            for (int j = 0; j < TNs; j++) w[j] = Ws[kk][tc * TNs + j];
#pragma unroll
            for (int i = 0; i < TMs; i++)
#pragma unroll
                for (int j = 0; j < TNs; j++) acc[i][j] += a[i] * w[j];
        }
        __syncthreads();
    }
#pragma unroll
    for (int i = 0; i < TMs; i++) {
        int m = bm + tr * TMs + i;
        if (m >= M) continue;
#pragma unroll
        for (int j = 0; j < TNs; j++) {
            int n = bn + tc * TNs + j;
            if (n >= N) continue;
            float v = acc[i][j] + bias[n];
            v = (v > 0.f) ? v : 0.1f * v;
            C[(size_t)m * ldc + n] = v;
        }
    }
}

// ------------------------------- launcher ----------------------------------
static inline dim3 wgrid(int M, int N) {
    return dim3((N + WBN - 1) / WBN, (M + WBM - 1) / WBM);
}

extern "C" void kernel_launch(void* const* d_in, const int* in_sizes, int n_in,
                              void* d_out, int out_size) {
    const int*   fnode      = (const int*)d_in[0];
    const int*   fmess      = (const int*)d_in[1];
    const int*   node_graph = (const int*)d_in[2];
    const int*   mess_graph = (const int*)d_in[3];
    const int*   root_idx   = (const int*)d_in[4];
    const float* emb        = (const float*)d_in[5];
    const float* W_z_w      = (const float*)d_in[6];
    const float* W_z_b      = (const float*)d_in[7];
    const float* W_r_w      = (const float*)d_in[8];
    const float* U_r_w      = (const float*)d_in[9];
    const float* U_r_b      = (const float*)d_in[10];
    const float* W_h_w      = (const float*)d_in[11];
    const float* W_h_b      = (const float*)d_in[12];
    const float* D1_w       = (const float*)d_in[13];
    const float* D1_b       = (const float*)d_in[14];
    const float* D2_w       = (const float*)d_in[15];
    const float* D2_b       = (const float*)d_in[16];
    const float* D3_w       = (const float*)d_in[17];
    const float* D3_b       = (const float*)d_in[18];
    const int*   depthp     = (n_in > 19) ? (const int*)d_in[19] : nullptr;
    float*       out        = (float*)d_out;

    float *fe, *x, *xzrh, *h, *hZU, *sumh, *z, *sumgh, *preh;
    float *Wpre, *Wstep, *Whh, *bias, *rv, *d1, *d2;
    cudaGetSymbolAddress((void**)&fe,    g_fe);
    cudaGetSymbolAddress((void**)&x,     g_x);
    cudaGetSymbolAddress((void**)&xzrh,  g_xzrh);
    cudaGetSymbolAddress((void**)&h,     g_h);
    cudaGetSymbolAddress((void**)&hZU,   g_hZU);
    cudaGetSymbolAddress((void**)&sumh,  g_sumh);
    cudaGetSymbolAddress((void**)&z,     g_z);
    cudaGetSymbolAddress((void**)&sumgh, g_sumgh);
    cudaGetSymbolAddress((void**)&preh,  g_preh);
    cudaGetSymbolAddress((void**)&Wpre,  g_Wpre);
    cudaGetSymbolAddress((void**)&Wstep, g_Wstep);
    cudaGetSymbolAddress((void**)&Whh,   g_Whh);
    cudaGetSymbolAddress((void**)&bias,  g_bias);
    cudaGetSymbolAddress((void**)&rv,    g_rv);
    cudaGetSymbolAddress((void**)&d1,    g_d1);
    cudaGetSymbolAddress((void**)&d2,    g_d2);

    const int TPB = 256;

    zero_kernel<<<(MROWS * LDX + TPB - 1) / TPB, TPB>>>(h, MROWS * LDX);

    {
        int n = 1350 * HH + 900 * HH + HH * HH + 1350;
        pack_kernel<<<(n + TPB - 1) / TPB, TPB>>>(W_z_w, W_h_w, W_r_w, U_r_w,
                                                  W_z_b, W_h_b, U_r_b,
                                                  Wpre, Wstep, Whh, bias);
    }

    gather_fe_kernel<<<(NNODES * HH + TPB - 1) / TPB, TPB>>>(emb, fnode, fe);
    gather_x_kernel<<<(NMESS * HH + TPB - 1) / TPB, TPB>>>(fe, fmess, x);

    wmma_gemm<<<wgrid(NMESS, 1350), 256>>>(x, LDX, Wpre, LDX,
                                           NMESS, 1350, HH, xzrh, LDPRE,
                                           nullptr, 0);

    step0_kernel<<<(NMESS * C2 + TPB - 1) / TPB, TPB>>>(xzrh, bias, h, depthp);

    for (int s = 1; s < MAXDEPTH; s++) {
        wmma_gemm<<<wgrid(NMESS, 900), 256>>>(h, LDX, Wstep, LDX,
                                              NMESS, 900, HH, hZU, LDZU,
                                              depthp, s);
        step_gather_kernel<<<(NMESS * C2 + TPB - 1) / TPB, TPB>>>(
            h, hZU, xzrh, bias, mess_graph, sumh, z, sumgh, depthp, s);
        wmma_gemm<<<wgrid(NMESS, HH), 256>>>(sumgh, LDX, Whh, LDX,
                                             NMESS, HH, HH, preh, LDX,
                                             depthp, s);
        h_update_kernel<<<(NMESS * C2 + TPB - 1) / TPB, TPB>>>(
            preh, xzrh, bias, z, sumh, h, depthp, s);
    }

    readout_kernel<<<(BB * HH + TPB - 1) / TPB, TPB>>>(fe, h, root_idx, node_graph, rv);
    disc_gemm<<<dim3((DHH + BN - 1) / BN, (BB + BM - 1) / BM), 256>>>(
        rv, 2 * HH, D1_w, 2 * HH, BB, DHH, 2 * HH, D1_b, d1, DHH);
    disc_gemm<<<dim3((DHH + BN - 1) / BN, (BB + BM - 1) / BM), 256>>>(
        d1, DHH, D2_w, DHH, BB, DHH, DHH, D2_b, d2, DHH);
    score_kernel<<<(BB * 32 + TPB - 1) / TPB, TPB>>>(d2, D3_w, D3_b, out);
}

// round 8
// speedup vs baseline: 2.3993x; 2.3993x over previous
#include <cuda_runtime.h>
#include <cuda_bf16.h>
#include <math.h>
#include <mma.h>

using namespace nvcuda;

// ---------------------------------------------------------------------------
// ScaffoldGAN JTNN GRU + discriminator. R8: compensated bf16 WMMA (m16n16k16).
//   * a*b ~= a_lo*b_hi + a_hi*b_lo + a_hi*b_hi, hi/lo bf16 split at smem store.
//   * All GEMM operands in zero-init padded scratch -> NO bounds checks.
//   * tf32-k8 mma.sync measured ~FFMA-rate on sm_103a (R6/R7); bf16-k16 is
//     the full-rate HMMA path.
// ---------------------------------------------------------------------------

#define HH     450
#define NNODES 4000
#define NMESS  6000
#define KNB    6
#define BB     256
#define DHH    450
#define MAXDEPTH 15
#define MROWS  6016

#define LDX   512
#define LDZU  1024
#define LDPRE 1536

// ---------------- device scratch (zero-initialized; pads never written) ----
__device__ float g_fe[NNODES * HH];
__device__ float g_x[MROWS * LDX];
__device__ float g_xzrh[MROWS * LDPRE];
__device__ float g_h[MROWS * LDX];
__device__ float g_hZU[MROWS * LDZU];
__device__ float g_sumh[MROWS * LDX];
__device__ float g_z[MROWS * LDX];
__device__ float g_sumgh[MROWS * LDX];
__device__ float g_preh[MROWS * LDX];
__device__ float g_Wpre[1408 * LDX];    // 11 N-tiles x 128
__device__ float g_Wstep[1024 * LDX];   // 8 N-tiles
__device__ float g_Whh[512 * LDX];      // 4 N-tiles
__device__ float g_bias[1536];
__device__ float g_rv[BB * 2 * HH];
__device__ float g_d1[BB * DHH];
__device__ float g_d2[BB * DHH];

// ---------------------------- small kernels --------------------------------
__global__ void zero_kernel(float* p, int n) {
    int i = blockIdx.x * blockDim.x + threadIdx.x;
    if (i < n) p[i] = 0.f;
}

__global__ void pack_kernel(const float* __restrict__ W_z_w,
                            const float* __restrict__ W_h_w,
                            const float* __restrict__ W_r_w,
                            const float* __restrict__ U_r_w,
                            const float* __restrict__ W_z_b,
                            const float* __restrict__ W_h_b,
                            const float* __restrict__ U_r_b,
                            float* __restrict__ Wpre,
                            float* __restrict__ Wstep,
                            float* __restrict__ Whh,
                            float* __restrict__ bias) {
    int i = blockIdx.x * blockDim.x + threadIdx.x;
    const int NPRE  = 1350 * HH;
    const int NSTEP = 900 * HH;
    const int NWHH  = HH * HH;
    if (i < NPRE) {
        int n = i / HH, k = i - n * HH;
        float v;
        if (n < HH)            v = W_z_w[n * 2 * HH + k];
        else if (n < 2 * HH)   v = W_h_w[(n - HH) * 2 * HH + k];
        else                   v = W_r_w[(n - 2 * HH) * HH + k];
        Wpre[n * LDX + k] = v;
    } else if (i < NPRE + NSTEP) {
        int j = i - NPRE;
        int n = j / HH, k = j - n * HH;
        float v = (n < HH) ? W_z_w[n * 2 * HH + HH + k]
                           : U_r_w[(n - HH) * HH + k];
        Wstep[n * LDX + k] = v;
    } else if (i < NPRE + NSTEP + NWHH) {
        int j = i - NPRE - NSTEP;
        int n = j / HH, k = j - n * HH;
        Whh[n * LDX + k] = W_h_w[n * 2 * HH + HH + k];
    } else if (i < NPRE + NSTEP + NWHH + 1350) {
        int n = i - NPRE - NSTEP - NWHH;
        bias[n] = (n < HH) ? W_z_b[n]
                : (n < 2 * HH) ? W_h_b[n - HH]
                : U_r_b[n - 2 * HH];
    }
}

__global__ void gather_fe_kernel(const float* __restrict__ emb,
                                 const int* __restrict__ fnode,
                                 float* __restrict__ fe) {
    int i = blockIdx.x * blockDim.x + threadIdx.x;
    if (i >= NNODES * HH) return;
    int r = i / HH, c = i - r * HH;
    fe[i] = emb[fnode[r] * HH + c];
}

__global__ void gather_x_kernel(const float* __restrict__ fe,
                                const int* __restrict__ fmess,
                                float* __restrict__ x) {
    int i = blockIdx.x * blockDim.x + threadIdx.x;
    if (i >= NMESS * HH) return;
    int r = i / HH, c = i - r * HH;
    x[r * LDX + c] = fe[fmess[r] * HH + c];
}

__device__ __forceinline__ float2 sigm2(float2 v) {
    return make_float2(1.f / (1.f + __expf(-v.x)), 1.f / (1.f + __expf(-v.y)));
}
__device__ __forceinline__ float2 tanh2(float2 v) {
    return make_float2(tanhf(v.x), tanhf(v.y));
}

#define C2 225

__global__ void step0_kernel(const float* __restrict__ xzrh,
                             const float* __restrict__ bias,
                             float* __restrict__ h,
                             const int* __restrict__ depthp) {
    if (depthp && __ldg(depthp) < 1) return;
    int i = blockIdx.x * blockDim.x + threadIdx.x;
    if (i >= NMESS * C2) return;
    int m = i / C2, c = i - m * C2;
    const float2* xp = (const float2*)xzrh + (size_t)m * (LDPRE / 2);
    const float2* bp = (const float2*)bias;
    float2 xz = xp[c],        bz = bp[c];
    float2 xh = xp[C2 + c],   bh = bp[C2 + c];
    float2 zv = sigm2(make_float2(xz.x + bz.x, xz.y + bz.y));
    float2 ph = tanh2(make_float2(xh.x + bh.x, xh.y + bh.y));
    float2 v = make_float2(zv.x * ph.x, zv.y * ph.y);
    if (m == 0) v = make_float2(0.f, 0.f);
    ((float2*)h)[(size_t)m * (LDX / 2) + c] = v;
}

__global__ void step_gather_kernel(const float* __restrict__ h,
                                   const float* __restrict__ hZU,
                                   const float* __restrict__ xzrh,
                                   const float* __restrict__ bias,
                                   const int* __restrict__ mg,
                                   float* __restrict__ sumh,
                                   float* __restrict__ z,
                                   float* __restrict__ sumgh,
                                   const int* __restrict__ depthp, int step) {
    if (depthp && step >= __ldg(depthp)) return;
    int i = blockIdx.x * blockDim.x + threadIdx.x;
    if (i >= NMESS * C2) return;
    int m = i / C2, c = i - m * C2;
    const float2* xp = (const float2*)xzrh + (size_t)m * (LDPRE / 2);
    const float2* bp = (const float2*)bias;
    float2 xr = xp[2 * C2 + c], br = bp[2 * C2 + c];
    float xr0 = xr.x + br.x, xr1 = xr.y + br.y;
    float2 sh = make_float2(0.f, 0.f);
    float2 sz = make_float2(0.f, 0.f);
    float2 sg = make_float2(0.f, 0.f);
    int idx[KNB];
#pragma unroll
    for (int k = 0; k < KNB; k++) idx[k] = mg[m * KNB + k];
#pragma unroll
    for (int k = 0; k < KNB; k++) {
        int j = idx[k];
        float2 hv = ((const float2*)h)[(size_t)j * (LDX / 2) + c];
        float2 zz = ((const float2*)hZU)[(size_t)j * (LDZU / 2) + c];
        float2 uu = ((const float2*)hZU)[(size_t)j * (LDZU / 2) + C2 + c];
        sh.x += hv.x; sh.y += hv.y;
        sz.x += zz.x; sz.y += zz.y;
        sg.x += hv.x / (1.f + __expf(-(xr0 + uu.x)));
        sg.y += hv.y / (1.f + __expf(-(xr1 + uu.y)));
    }
    size_t o = (size_t)m * (LDX / 2) + c;
    ((float2*)sumh)[o] = sh;
    float2 xz = xp[c], bz = bp[c];
    ((float2*)z)[o] = sigm2(make_float2(sz.x + xz.x + bz.x, sz.y + xz.y + bz.y));
    ((float2*)sumgh)[o] = sg;
}

__global__ void h_update_kernel(const float* __restrict__ preh,
                                const float* __restrict__ xzrh,
                                const float* __restrict__ bias,
                                const float* __restrict__ z,
                                const float* __restrict__ sumh,
                                float* __restrict__ h,
                                const int* __restrict__ depthp, int step) {
    if (depthp && step >= __ldg(depthp)) return;
    int i = blockIdx.x * blockDim.x + threadIdx.x;
    if (i >= NMESS * C2) return;
    int m = i / C2, c = i - m * C2;
    size_t o = (size_t)m * (LDX / 2) + c;
    float2 pv = ((const float2*)preh)[o];
    float2 xh = ((const float2*)xzrh)[(size_t)m * (LDPRE / 2) + C2 + c];
    float2 bh = ((const float2*)bias)[C2 + c];
    float2 ph = tanh2(make_float2(pv.x + xh.x + bh.x, pv.y + xh.y + bh.y));
    float2 zv = ((const float2*)z)[o];
    float2 sh = ((const float2*)sumh)[o];
    float2 v = make_float2((1.f - zv.x) * sh.x + zv.x * ph.x,
                           (1.f - zv.y) * sh.y + zv.y * ph.y);
    if (m == 0) v = make_float2(0.f, 0.f);
    ((float2*)h)[o] = v;
}

__global__ void readout_kernel(const float* __restrict__ fe,
                               const float* __restrict__ h,
                               const int* __restrict__ root,
                               const int* __restrict__ ng,
                               float* __restrict__ rv) {
    int i = blockIdx.x * blockDim.x + threadIdx.x;
    if (i >= BB * HH) return;
    int b = i / HH, c = i - b * HH;
    int node = root[b];
    rv[b * 2 * HH + c] = fe[node * HH + c];
    float s = 0.f;
#pragma unroll
    for (int k = 0; k < KNB; k++)
        s += h[(size_t)ng[node * KNB + k] * LDX + c];
    rv[b * 2 * HH + HH + c] = s;
}

__global__ void score_kernel(const float* __restrict__ h2,
                             const float* __restrict__ w,
                             const float* __restrict__ b3,
                             float* __restrict__ out) {
    int gt = blockIdx.x * blockDim.x + threadIdx.x;
    int warp = gt >> 5, lane = gt & 31;
    if (warp >= BB) return;
    float s = 0.f;
    for (int k = lane; k < DHH; k += 32) s += h2[warp * DHH + k] * w[k];
#pragma unroll
    for (int o = 16; o; o >>= 1) s += __shfl_xor_sync(0xffffffffu, s, o);
    if (lane == 0) out[warp] = s + b3[0];
}

// ------------------- compensated bf16 WMMA GEMM (m16n16k16) ----------------
// C = A @ W^T. Operands MUST be padded scratch (no guards!):
//   A rows: full M-tiles within buffer; W rows: full N-tiles within buffer;
//   lda/ldw = LDX (512) >= ceil(K,32); pads are zero.
#define WBM 128
#define WBN 128
#define WBK 32
#define KPADB 40   // bf16 elems per row: 80B, mult of 16B

__device__ __forceinline__ void split8_store(float4 v0, float4 v1,
                                             __nv_bfloat16* hip,
                                             __nv_bfloat16* lop) {
    float f[8] = {v0.x, v0.y, v0.z, v0.w, v1.x, v1.y, v1.z, v1.w};
    __nv_bfloat16 hi[8], lo[8];
#pragma unroll
    for (int e = 0; e < 8; e++) {
        hi[e] = __float2bfloat16(f[e]);
        lo[e] = __float2bfloat16(f[e] - __bfloat162float(hi[e]));
    }
    *reinterpret_cast<float4*>(hip) = *reinterpret_cast<float4*>(hi);
    *reinterpret_cast<float4*>(lop) = *reinterpret_cast<float4*>(lo);
}

__global__ __launch_bounds__(256)
void wmma_gemm(const float* __restrict__ A, int lda,
               const float* __restrict__ W, int ldw,
               int M, int N, int K,
               float* __restrict__ C, int ldc,
               const int* __restrict__ depthp, int step) {
    if (depthp && step >= __ldg(depthp)) return;

    __shared__ __align__(16) __nv_bfloat16 Ahi[WBM][KPADB];
    __shared__ __align__(16) __nv_bfloat16 Alo[WBM][KPADB];
    __shared__ __align__(16) __nv_bfloat16 Bhi[WBN][KPADB];
    __shared__ __align__(16) __nv_bfloat16 Blo[WBN][KPADB];

    const int tid = threadIdx.x;
    const int wid = tid >> 5;
    const int wm = wid & 1;       // 2 warps along M (64 rows)
    const int wn = wid >> 1;      // 4 warps along N (32 cols)
    const int bm = blockIdx.y * WBM;
    const int bn = blockIdx.x * WBN;

    wmma::fragment<wmma::accumulator, 16, 16, 16, float> acc[4][2];
#pragma unroll
    for (int i = 0; i < 4; i++)
#pragma unroll
        for (int j = 0; j < 2; j++) wmma::fill_fragment(acc[i][j], 0.f);

    // 2 slots/thread: rows r and r+64, same kq (8-float chunk of 32-wide k)
    const int r0 = tid >> 2;             // 0..63
    const int kq = (tid & 3) * 8;        // 0,8,16,24

    const int NT = (K + WBK - 1) / WBK;

    // prefetch tile 0
    float4 ra[2][2], rw[2][2];
#pragma unroll
    for (int s = 0; s < 2; s++) {
        const float* pa = A + (size_t)(bm + r0 + s * 64) * lda + kq;
        ra[s][0] = *reinterpret_cast<const float4*>(pa);
        ra[s][1] = *reinterpret_cast<const float4*>(pa + 4);
        const float* pw = W + (size_t)(bn + r0 + s * 64) * ldw + kq;
        rw[s][0] = *reinterpret_cast<const float4*>(pw);
        rw[s][1] = *reinterpret_cast<const float4*>(pw + 4);
    }

    for (int t0 = 0; t0 < NT; t0++) {
#pragma unroll
        for (int s = 0; s < 2; s++) {
            split8_store(ra[s][0], ra[s][1], &Ahi[r0 + s * 64][kq], &Alo[r0 + s * 64][kq]);
            split8_store(rw[s][0], rw[s][1], &Bhi[r0 + s * 64][kq], &Blo[r0 + s * 64][kq]);
        }
        __syncthreads();

        if (t0 + 1 < NT) {
            int k0 = (t0 + 1) * WBK + kq;
#pragma unroll
            for (int s = 0; s < 2; s++) {
                const float* pa = A + (size_t)(bm + r0 + s * 64) * lda + k0;
                ra[s][0] = *reinterpret_cast<const float4*>(pa);
                ra[s][1] = *reinterpret_cast<const float4*>(pa + 4);
                const float* pw = W + (size_t)(bn + r0 + s * 64) * ldw + k0;
                rw[s][0] = *reinterpret_cast<const float4*>(pw);
                rw[s][1] = *reinterpret_cast<const float4*>(pw + 4);
            }
        }

#pragma unroll
        for (int kk = 0; kk < WBK; kk += 16) {
            wmma::fragment<wmma::matrix_b, 16, 16, 16, __nv_bfloat16,
                           wmma::col_major> bhi[2], blo[2];
#pragma unroll
            for (int j = 0; j < 2; j++) {
                wmma::load_matrix_sync(bhi[j], &Bhi[wn * 32 + j * 16][kk], KPADB);
                wmma::load_matrix_sync(blo[j], &Blo[wn * 32 + j * 16][kk], KPADB);
            }
#pragma unroll
            for (int i = 0; i < 4; i++) {
                wmma::fragment<wmma::matrix_a, 16, 16, 16, __nv_bfloat16,
                               wmma::row_major> ahi, alo;
                wmma::load_matrix_sync(ahi, &Ahi[wm * 64 + i * 16][kk], KPADB);
                wmma::load_matrix_sync(alo, &Alo[wm * 64 + i * 16][kk], KPADB);
#pragma unroll
                for (int j = 0; j < 2; j++) {
                    wmma::mma_sync(acc[i][j], alo, bhi[j], acc[i][j]);
                    wmma::mma_sync(acc[i][j], ahi, blo[j], acc[i][j]);
                    wmma::mma_sync(acc[i][j], ahi, bhi[j], acc[i][j]);
                }
            }
        }
        __syncthreads();
    }

#pragma unroll
    for (int i = 0; i < 4; i++)
#pragma unroll
        for (int j = 0; j < 2; j++) {
            float* cp = C + (size_t)(bm + wm * 64 + i * 16) * ldc
                          + bn + wn * 32 + j * 16;
            wmma::store_matrix_sync(cp, acc[i][j], ldc, wmma::mem_row_major);
        }
}

// ------------------ fp32 SIMT GEMM (discriminator only) --------------------
#define BM 64
#define BN 64
#define BKK 16
#define TMs 4
#define TNs 4

__global__ __launch_bounds__(256)
void disc_gemm(const float* __restrict__ A, int lda,
               const float* __restrict__ W, int ldw,
               int M, int N, int K,
               const float* __restrict__ bias,
               float* __restrict__ C, int ldc) {
    __shared__ float As[BKK][BM];
    __shared__ float Ws[BKK][BN];
    int bm = blockIdx.y * BM, bn = blockIdx.x * BN;
    int tid = threadIdx.x;
    int tr = tid >> 4, tc = tid & 15;
    float acc[TMs][TNs];
#pragma unroll
    for (int i = 0; i < TMs; i++)
#pragma unroll
        for (int j = 0; j < TNs; j++) acc[i][j] = 0.f;
    for (int k0 = 0; k0 < K; k0 += BKK) {
#pragma unroll
        for (int t = 0; t < 4; t++) {
            int l = tid + t * 256;
            int i = l >> 4, j = l & 15;
            int gm = bm + i, gk = k0 + j;
            As[j][i] = (gm < M && gk < K) ? A[(size_t)gm * lda + gk] : 0.f;
        }
#pragma unroll
        for (int t = 0; t < 4; t++) {
            int l = tid + t * 256;
            int i = l >> 4, j = l & 15;
            int gn = bn + i, gk = k0 + j;
            Ws[j][i] = (gn < N && gk < K) ? W[(size_t)gn * ldw + gk] : 0.f;
        }
        __syncthreads();
#pragma unroll
        for (int kk = 0; kk < BKK; kk++) {
            float a[TMs], w[TNs];
#pragma unroll
            for (int i = 0; i < TMs; i++) a[i] = As[kk][tr * TMs + i];
#pragma unroll
            for (int j = 0; j < TNs; j++) w[j] = Ws[kk][tc * TNs + j];
#pragma unroll
            for (int i = 0; i < TMs; i++)
#pragma unroll
                for (int j = 0; j < TNs; j++) acc[i][j] += a[i] * w[j];
        }
        __syncthreads();
    }
#pragma unroll
    for (int i = 0; i < TMs; i++) {
        int m = bm + tr * TMs + i;
        if (m >= M) continue;
#pragma unroll
        for (int j = 0; j < TNs; j++) {
            int n = bn + tc * TNs + j;
            if (n >= N) continue;
            float v = acc[i][j] + bias[n];
            v = (v > 0.f) ? v : 0.1f * v;
            C[(size_t)m * ldc + n] = v;
        }
    }
}

// ------------------------------- launcher ----------------------------------
static inline dim3 wgrid(int M, int N) {
    return dim3((N + WBN - 1) / WBN, (M + WBM - 1) / WBM);
}

extern "C" void kernel_launch(void* const* d_in, const int* in_sizes, int n_in,
                              void* d_out, int out_size) {
    const int*   fnode      = (const int*)d_in[0];
    const int*   fmess      = (const int*)d_in[1];
    const int*   node_graph = (const int*)d_in[2];
    const int*   mess_graph = (const int*)d_in[3];
    const int*   root_idx   = (const int*)d_in[4];
    const float* emb        = (const float*)d_in[5];
    const float* W_z_w      = (const float*)d_in[6];
    const float* W_z_b      = (const float*)d_in[7];
    const float* W_r_w      = (const float*)d_in[8];
    const float* U_r_w      = (const float*)d_in[9];
    const float* U_r_b      = (const float*)d_in[10];
    const float* W_h_w      = (const float*)d_in[11];
    const float* W_h_b      = (const float*)d_in[12];
    const float* D1_w       = (const float*)d_in[13];
    const float* D1_b       = (const float*)d_in[14];
    const float* D2_w       = (const float*)d_in[15];
    const float* D2_b       = (const float*)d_in[16];
    const float* D3_w       = (const float*)d_in[17];
    const float* D3_b       = (const float*)d_in[18];
    const int*   depthp     = (n_in > 19) ? (const int*)d_in[19] : nullptr;
    float*       out        = (float*)d_out;

    float *fe, *x, *xzrh, *h, *hZU, *sumh, *z, *sumgh, *preh;
    float *Wpre, *Wstep, *Whh, *bias, *rv, *d1, *d2;
    cudaGetSymbolAddress((void**)&fe,    g_fe);
    cudaGetSymbolAddress((void**)&x,     g_x);
    cudaGetSymbolAddress((void**)&xzrh,  g_xzrh);
    cudaGetSymbolAddress((void**)&h,     g_h);
    cudaGetSymbolAddress((void**)&hZU,   g_hZU);
    cudaGetSymbolAddress((void**)&sumh,  g_sumh);
    cudaGetSymbolAddress((void**)&z,     g_z);
    cudaGetSymbolAddress((void**)&sumgh, g_sumgh);
    cudaGetSymbolAddress((void**)&preh,  g_preh);
    cudaGetSymbolAddress((void**)&Wpre,  g_Wpre);
    cudaGetSymbolAddress((void**)&Wstep, g_Wstep);
    cudaGetSymbolAddress((void**)&Whh,   g_Whh);
    cudaGetSymbolAddress((void**)&bias,  g_bias);
    cudaGetSymbolAddress((void**)&rv,    g_rv);
    cudaGetSymbolAddress((void**)&d1,    g_d1);
    cudaGetSymbolAddress((void**)&d2,    g_d2);

    const int TPB = 256;

    zero_kernel<<<(MROWS * LDX + TPB - 1) / TPB, TPB>>>(h, MROWS * LDX);

    {
        int n = 1350 * HH + 900 * HH + HH * HH + 1350;
        pack_kernel<<<(n + TPB - 1) / TPB, TPB>>>(W_z_w, W_h_w, W_r_w, U_r_w,
                                                  W_z_b, W_h_b, U_r_b,
                                                  Wpre, Wstep, Whh, bias);
    }

    gather_fe_kernel<<<(NNODES * HH + TPB - 1) / TPB, TPB>>>(emb, fnode, fe);
    gather_x_kernel<<<(NMESS * HH + TPB - 1) / TPB, TPB>>>(fe, fmess, x);

    wmma_gemm<<<wgrid(NMESS, 1350), 256>>>(x, LDX, Wpre, LDX,
                                           NMESS, 1350, HH, xzrh, LDPRE,
                                           nullptr, 0);

    step0_kernel<<<(NMESS * C2 + TPB - 1) / TPB, TPB>>>(xzrh, bias, h, depthp);

    for (int s = 1; s < MAXDEPTH; s++) {
        wmma_gemm<<<wgrid(NMESS, 900), 256>>>(h, LDX, Wstep, LDX,
                                              NMESS, 900, HH, hZU, LDZU,
                                              depthp, s);
        step_gather_kernel<<<(NMESS * C2 + TPB - 1) / TPB, TPB>>>(
            h, hZU, xzrh, bias, mess_graph, sumh, z, sumgh, depthp, s);
        wmma_gemm<<<wgrid(NMESS, HH), 256>>>(sumgh, LDX, Whh, LDX,
                                             NMESS, HH, HH, preh, LDX,
                                             depthp, s);
        h_update_kernel<<<(NMESS * C2 + TPB - 1) / TPB, TPB>>>(
            preh, xzrh, bias, z, sumh, h, depthp, s);
    }

    readout_kernel<<<(BB * HH + TPB - 1) / TPB, TPB>>>(fe, h, root_idx, node_graph, rv);
    disc_gemm<<<dim3((DHH + BN - 1) / BN, (BB + BM - 1) / BM), 256>>>(
        rv, 2 * HH, D1_w, 2 * HH, BB, DHH, 2 * HH, D1_b, d1, DHH);
    disc_gemm<<<dim3((DHH + BN - 1) / BN, (BB + BM - 1) / BM), 256>>>(
        d1, DHH, D2_w, DHH, BB, DHH, DHH, D2_b, d2, DHH);
    score_kernel<<<(BB * 32 + TPB - 1) / TPB, TPB>>>(d2, D3_w, D3_b, out);
}

// round 11
// speedup vs baseline: 2.4003x; 1.0004x over previous
#include <cuda_runtime.h>
#include <cuda_bf16.h>
#include <cstdint>
#include <math.h>
#include <mma.h>

using namespace nvcuda;

// ---------------------------------------------------------------------------
// ScaffoldGAN JTNN GRU + discriminator. R11: bf16 HMMA GEMM, operands
// PRE-SPLIT to bf16 hi/lo at producers (weights once; activations in the
// elementwise kernels / fused epilogue). GEMM inner loop = cp.async +
// ldmatrix + MMA only. 64x64 warp tiles (4 warps). K=480. GRU h-update
// fused into GEMM epilogue (mode 3). tcgen05 unavailable (ptxas targets
// compute_103, no 'a' features) -- proven R10.
// ---------------------------------------------------------------------------

#define HH     450
#define NNODES 4000
#define NMESS  6000
#define KNB    6
#define BB     256
#define DHH    450
#define MAXDEPTH 15
#define MROWS  6016

#define LDX   512
#define LDZU  1024
#define LDPRE 1536

#define KK    480
#define NTILE 15          // KK / 32
#define KPADB 40          // bf16 elems per smem row (80 B)
#define STG   10240       // one smem operand buffer: 128*KPADB*2
#define SMTOT 81920       // 8 buffers (2 stages x 4 operands); >= 128*132*4

// ---------------- device scratch (zero-initialized; pads never written) ----
__device__ float g_fe[NNODES * HH];
__device__ float g_xzrh[MROWS * LDPRE];     // xz | xh | xr (fp32, GEMM out)
__device__ float g_h[MROWS * LDX];          // fp32 h (gather/readout)
__device__ float g_hZU[MROWS * LDZU];
__device__ float g_sumh[MROWS * LDX];
__device__ float g_z[MROWS * LDX];
__device__ float g_bias[1536];
__device__ float g_rv[BB * 2 * HH];
__device__ float g_d1[BB * DHH];
__device__ float g_d2[BB * DHH];
// bf16 hi/lo GEMM operands
__device__ __nv_bfloat16 g_xhi[MROWS * LDX];
__device__ __nv_bfloat16 g_xlo[MROWS * LDX];
__device__ __nv_bfloat16 g_hhi[MROWS * LDX];
__device__ __nv_bfloat16 g_hlo[MROWS * LDX];
__device__ __nv_bfloat16 g_sghi[MROWS * LDX];
__device__ __nv_bfloat16 g_sglo[MROWS * LDX];
__device__ __nv_bfloat16 g_Wpre_hi[1408 * LDX];
__device__ __nv_bfloat16 g_Wpre_lo[1408 * LDX];
__device__ __nv_bfloat16 g_Wstep_hi[1024 * LDX];
__device__ __nv_bfloat16 g_Wstep_lo[1024 * LDX];
__device__ __nv_bfloat16 g_Whh_hi[512 * LDX];
__device__ __nv_bfloat16 g_Whh_lo[512 * LDX];

// --------------------------- helpers ---------------------------------------
__device__ __forceinline__ uint32_t smem_u32(const void* p) {
    uint32_t a;
    asm("{ .reg .u64 t; cvta.to.shared.u64 t, %1; cvt.u32.u64 %0, t; }"
        : "=r"(a) : "l"(p));
    return a;
}
#define CP16(d, s) \
    asm volatile("cp.async.cg.shared.global [%0], [%1], 16;" \
                 :: "r"(d), "l"(s) : "memory")
#define CP_COMMIT asm volatile("cp.async.commit_group;" ::: "memory")
#define CP_WAIT1  asm volatile("cp.async.wait_group 1;" ::: "memory")
#define CP_WAIT0  asm volatile("cp.async.wait_group 0;" ::: "memory")

__device__ __forceinline__ void split1(float v, __nv_bfloat16& hi, __nv_bfloat16& lo) {
    hi = __float2bfloat16(v);
    lo = __float2bfloat16(v - __bfloat162float(hi));
}
__device__ __forceinline__ float2 sigm2(float2 v) {
    return make_float2(1.f / (1.f + __expf(-v.x)), 1.f / (1.f + __expf(-v.y)));
}
__device__ __forceinline__ float2 tanh2(float2 v) {
    return make_float2(tanhf(v.x), tanhf(v.y));
}

// ---------------------------- small kernels --------------------------------
__global__ void zero_kernel(float* p, int n) {
    int i = blockIdx.x * blockDim.x + threadIdx.x;
    if (i < n) p[i] = 0.f;
}

__global__ void pack_kernel(const float* __restrict__ W_z_w,
                            const float* __restrict__ W_h_w,
                            const float* __restrict__ W_r_w,
                            const float* __restrict__ U_r_w,
                            const float* __restrict__ W_z_b,
                            const float* __restrict__ W_h_b,
                            const float* __restrict__ U_r_b,
                            __nv_bfloat16* __restrict__ Wpre_hi,
                            __nv_bfloat16* __restrict__ Wpre_lo,
                            __nv_bfloat16* __restrict__ Wstep_hi,
                            __nv_bfloat16* __restrict__ Wstep_lo,
                            __nv_bfloat16* __restrict__ Whh_hi,
                            __nv_bfloat16* __restrict__ Whh_lo,
                            float* __restrict__ bias) {
    int i = blockIdx.x * blockDim.x + threadIdx.x;
    const int NPRE  = 1350 * HH;
    const int NSTEP = 900 * HH;
    const int NWHH  = HH * HH;
    if (i < NPRE) {
        int n = i / HH, k = i - n * HH;
        float v;
        if (n < HH)            v = W_z_w[n * 2 * HH + k];
        else if (n < 2 * HH)   v = W_h_w[(n - HH) * 2 * HH + k];
        else                   v = W_r_w[(n - 2 * HH) * HH + k];
        split1(v, Wpre_hi[n * LDX + k], Wpre_lo[n * LDX + k]);
    } else if (i < NPRE + NSTEP) {
        int j = i - NPRE;
        int n = j / HH, k = j - n * HH;
        float v = (n < HH) ? W_z_w[n * 2 * HH + HH + k]
                           : U_r_w[(n - HH) * HH + k];
        split1(v, Wstep_hi[n * LDX + k], Wstep_lo[n * LDX + k]);
    } else if (i < NPRE + NSTEP + NWHH) {
        int j = i - NPRE - NSTEP;
        int n = j / HH, k = j - n * HH;
        float v = W_h_w[n * 2 * HH + HH + k];
        split1(v, Whh_hi[n * LDX + k], Whh_lo[n * LDX + k]);
    } else if (i < NPRE + NSTEP + NWHH + 1350) {
        int n = i - NPRE - NSTEP - NWHH;
        bias[n] = (n < HH) ? W_z_b[n]
                : (n < 2 * HH) ? W_h_b[n - HH]
                : U_r_b[n - 2 * HH];
    }
}

__global__ void gather_fe_kernel(const float* __restrict__ emb,
                                 const int* __restrict__ fnode,
                                 float* __restrict__ fe) {
    int i = blockIdx.x * blockDim.x + threadIdx.x;
    if (i >= NNODES * HH) return;
    int r = i / HH, c = i - r * HH;
    fe[i] = emb[fnode[r] * HH + c];
}

__global__ void gather_x_kernel(const float* __restrict__ fe,
                                const int* __restrict__ fmess,
                                __nv_bfloat16* __restrict__ xhi,
                                __nv_bfloat16* __restrict__ xlo) {
    int i = blockIdx.x * blockDim.x + threadIdx.x;
    if (i >= NMESS * HH) return;
    int r = i / HH, c = i - r * HH;
    float v = fe[fmess[r] * HH + c];
    split1(v, xhi[(size_t)r * LDX + c], xlo[(size_t)r * LDX + c]);
}

#define C2 225

// step 0: h = mask * sigmoid(xz+bz) * tanh(xh+bh); writes fp32 + hi/lo
__global__ void step0_kernel(const float* __restrict__ xzrh,
                             const float* __restrict__ bias,
                             float* __restrict__ h,
                             __nv_bfloat16* __restrict__ hhi,
                             __nv_bfloat16* __restrict__ hlo,
                             const int* __restrict__ depthp) {
    if (depthp && __ldg(depthp) < 1) return;
    int i = blockIdx.x * blockDim.x + threadIdx.x;
    if (i >= NMESS * C2) return;
    int m = i / C2, c = i - m * C2;
    const float2* xp = (const float2*)xzrh + (size_t)m * (LDPRE / 2);
    const float2* bp = (const float2*)bias;
    float2 xz = xp[c],        bz = bp[c];
    float2 xh = xp[C2 + c],   bh = bp[C2 + c];
    float2 zv = sigm2(make_float2(xz.x + bz.x, xz.y + bz.y));
    float2 ph = tanh2(make_float2(xh.x + bh.x, xh.y + bh.y));
    float2 v = make_float2(zv.x * ph.x, zv.y * ph.y);
    if (m == 0) v = make_float2(0.f, 0.f);
    size_t o = (size_t)m * (LDX / 2) + c;
    ((float2*)h)[o] = v;
    __nv_bfloat162 hi2, lo2;
    split1(v.x, hi2.x, lo2.x);
    split1(v.y, hi2.y, lo2.y);
    ((__nv_bfloat162*)hhi)[o] = hi2;
    ((__nv_bfloat162*)hlo)[o] = lo2;
}

// Fused gather: sum_h; z = sigmoid(sum(hWz)+xz+bz); sum_gh -> bf16 hi/lo
__global__ void step_gather_kernel(const float* __restrict__ h,
                                   const float* __restrict__ hZU,
                                   const float* __restrict__ xzrh,
                                   const float* __restrict__ bias,
                                   const int* __restrict__ mg,
                                   float* __restrict__ sumh,
                                   float* __restrict__ z,
                                   __nv_bfloat16* __restrict__ sghi,
                                   __nv_bfloat16* __restrict__ sglo,
                                   const int* __restrict__ depthp, int step) {
    if (depthp && step >= __ldg(depthp)) return;
    int i = blockIdx.x * blockDim.x + threadIdx.x;
    if (i >= NMESS * C2) return;
    int m = i / C2, c = i - m * C2;
    const float2* xp = (const float2*)xzrh + (size_t)m * (LDPRE / 2);
    const float2* bp = (const float2*)bias;
    float2 xr = xp[2 * C2 + c], br = bp[2 * C2 + c];
    float xr0 = xr.x + br.x, xr1 = xr.y + br.y;
    float2 sh = make_float2(0.f, 0.f);
    float2 sz = make_float2(0.f, 0.f);
    float2 sg = make_float2(0.f, 0.f);
    int idx[KNB];
#pragma unroll
    for (int k = 0; k < KNB; k++) idx[k] = mg[m * KNB + k];
#pragma unroll
    for (int k = 0; k < KNB; k++) {
        int j = idx[k];
        float2 hv = ((const float2*)h)[(size_t)j * (LDX / 2) + c];
        float2 zz = ((const float2*)hZU)[(size_t)j * (LDZU / 2) + c];
        float2 uu = ((const float2*)hZU)[(size_t)j * (LDZU / 2) + C2 + c];
        sh.x += hv.x; sh.y += hv.y;
        sz.x += zz.x; sz.y += zz.y;
        sg.x += hv.x / (1.f + __expf(-(xr0 + uu.x)));
        sg.y += hv.y / (1.f + __expf(-(xr1 + uu.y)));
    }
    size_t o = (size_t)m * (LDX / 2) + c;
    ((float2*)sumh)[o] = sh;
    float2 xz = xp[c], bz = bp[c];
    ((float2*)z)[o] = sigm2(make_float2(sz.x + xz.x + bz.x, sz.y + xz.y + bz.y));
    __nv_bfloat162 hi2, lo2;
    split1(sg.x, hi2.x, lo2.x);
    split1(sg.y, hi2.y, lo2.y);
    ((__nv_bfloat162*)sghi)[o] = hi2;
    ((__nv_bfloat162*)sglo)[o] = lo2;
}

__global__ void readout_kernel(const float* __restrict__ fe,
                               const float* __restrict__ h,
                               const int* __restrict__ root,
                               const int* __restrict__ ng,
                               float* __restrict__ rv) {
    int i = blockIdx.x * blockDim.x + threadIdx.x;
    if (i >= BB * HH) return;
    int b = i / HH, c = i - b * HH;
    int node = root[b];
    rv[b * 2 * HH + c] = fe[node * HH + c];
    float s = 0.f;
#pragma unroll
    for (int k = 0; k < KNB; k++)
        s += h[(size_t)ng[node * KNB + k] * LDX + c];
    rv[b * 2 * HH + HH + c] = s;
}

__global__ void score_kernel(const float* __restrict__ h2,
                             const float* __restrict__ w,
                             const float* __restrict__ b3,
                             float* __restrict__ out) {
    int gt = blockIdx.x * blockDim.x + threadIdx.x;
    int warp = gt >> 5, lane = gt & 31;
    if (warp >= BB) return;
    float s = 0.f;
    for (int k = lane; k < DHH; k += 32) s += h2[warp * DHH + k] * w[k];
#pragma unroll
    for (int o = 16; o; o >>= 1) s += __shfl_xor_sync(0xffffffffu, s, o);
    if (lane == 0) out[warp] = s + b3[0];
}

// ----------------- bf16 HMMA GEMM, pre-split operands ----------------------
// acc = Ahi@Bhi^T + Ahi@Blo^T + Alo@Bhi^T over K=480; operands padded, no
// guards. mode 0: C = acc.  mode 3: GRU h-update (fp32 h + bf16 hi/lo),
// stores guarded to n < 450 so h pads stay zero.
__global__ __launch_bounds__(128)
void mma_gemm(const __nv_bfloat16* __restrict__ Ah,
              const __nv_bfloat16* __restrict__ Al,
              const __nv_bfloat16* __restrict__ Bh,
              const __nv_bfloat16* __restrict__ Bl,
              int mode,
              const float* __restrict__ pre,     // xzrh + HH (mode 3)
              const float* __restrict__ biasp,   // bias + HH (mode 3)
              const float* __restrict__ z,
              const float* __restrict__ sumh,
              float* __restrict__ C, int ldc,    // mode 0 out / mode 3 h fp32
              __nv_bfloat16* __restrict__ hhi,
              __nv_bfloat16* __restrict__ hlo,
              const int* __restrict__ depthp, int step) {
    if (depthp && step >= __ldg(depthp)) return;

    extern __shared__ __align__(16) char smem[];
    const uint32_t sb = smem_u32(smem);
    const int tid = threadIdx.x;
    const int warp = tid >> 5;
    const int wm = warp & 1;    // 2 x 64-row halves
    const int wn = warp >> 1;   // 2 x 64-col halves
    const int bm = blockIdx.y * 128;
    const int bn = blockIdx.x * 128;

    wmma::fragment<wmma::accumulator, 16, 16, 16, float> acc[4][4];
#pragma unroll
    for (int i = 0; i < 4; i++)
#pragma unroll
        for (int j = 0; j < 4; j++) wmma::fill_fragment(acc[i][j], 0.f);

    // ---- async loader: 16 x 16B per thread per stage ----
    auto load_stage = [&](int stg, int kc) {
        uint32_t base = sb + (uint32_t)stg * 4 * STG;
#pragma unroll
        for (int g = 0; g < 4; g++) {
            int u = tid + g * 128;
            int row = u >> 2, q = u & 3;
            uint32_t so = (uint32_t)(row * KPADB + q * 8) * 2;
            size_t ao = (size_t)(bm + row) * LDX + kc + q * 8;
            size_t bo = (size_t)(bn + row) * LDX + kc + q * 8;
            CP16(base + so,            Ah + ao);
            CP16(base + STG + so,      Al + ao);
            CP16(base + 2 * STG + so,  Bh + bo);
            CP16(base + 3 * STG + so,  Bl + bo);
        }
    };

    auto do_mma = [&](int stg) {
        const __nv_bfloat16* SAh = (const __nv_bfloat16*)(smem + (size_t)stg * 4 * STG);
        const __nv_bfloat16* SAl = (const __nv_bfloat16*)(smem + (size_t)stg * 4 * STG + STG);
        const __nv_bfloat16* SBh = (const __nv_bfloat16*)(smem + (size_t)stg * 4 * STG + 2 * STG);
        const __nv_bfloat16* SBl = (const __nv_bfloat16*)(smem + (size_t)stg * 4 * STG + 3 * STG);
#pragma unroll
        for (int kk = 0; kk < 32; kk += 16) {
            wmma::fragment<wmma::matrix_b, 16, 16, 16, __nv_bfloat16,
                           wmma::col_major> bhi[4], blo[4];
#pragma unroll
            for (int j = 0; j < 4; j++) {
                wmma::load_matrix_sync(bhi[j], SBh + (wn * 64 + j * 16) * KPADB + kk, KPADB);
                wmma::load_matrix_sync(blo[j], SBl + (wn * 64 + j * 16) * KPADB + kk, KPADB);
            }
#pragma unroll
            for (int i = 0; i < 4; i++) {
                wmma::fragment<wmma::matrix_a, 16, 16, 16, __nv_bfloat16,
                               wmma::row_major> ahi, alo;
                wmma::load_matrix_sync(ahi, SAh + (wm * 64 + i * 16) * KPADB + kk, KPADB);
                wmma::load_matrix_sync(alo, SAl + (wm * 64 + i * 16) * KPADB + kk, KPADB);
#pragma unroll
                for (int j = 0; j < 4; j++) {
                    wmma::mma_sync(acc[i][j], alo, bhi[j], acc[i][j]);
                    wmma::mma_sync(acc[i][j], ahi, blo[j], acc[i][j]);
                    wmma::mma_sync(acc[i][j], ahi, bhi[j], acc[i][j]);
                }
            }
        }
    };

    load_stage(0, 0);
    CP_COMMIT;
    for (int ch = 0; ch < NTILE; ch++) {
        if (ch + 1 < NTILE) {
            load_stage((ch + 1) & 1, (ch + 1) * 32);
            CP_COMMIT;
            CP_WAIT1;
        } else {
            CP_WAIT0;
        }
        __syncthreads();
        do_mma(ch & 1);
        __syncthreads();
    }

    if (mode == 0) {
#pragma unroll
        for (int i = 0; i < 4; i++)
#pragma unroll
            for (int j = 0; j < 4; j++) {
                float* cp = C + (size_t)(bm + wm * 64 + i * 16) * ldc
                              + bn + wn * 64 + j * 16;
                wmma::store_matrix_sync(cp, acc[i][j], ldc, wmma::mem_row_major);
            }
    } else {
        // stage acc through smem, then fused GRU update (guard n < 450)
        float* Cs = (float*)smem;
#pragma unroll
        for (int i = 0; i < 4; i++)
#pragma unroll
            for (int j = 0; j < 4; j++) {
                float* cp = Cs + (size_t)(wm * 64 + i * 16) * 132
                               + wn * 64 + j * 16;
                wmma::store_matrix_sync(cp, acc[i][j], 132, wmma::mem_row_major);
            }
        __syncthreads();
        int n = bn + tid;
        if (n < HH) {
            for (int row = 0; row < 128; row++) {
                int m = bm + row;
                float accv = Cs[(size_t)row * 132 + tid];
                float ph = tanhf(accv + pre[(size_t)m * LDPRE + n] + biasp[n]);
                float zv = z[(size_t)m * LDX + n];
                float sh = sumh[(size_t)m * LDX + n];
                float v = (1.f - zv) * sh + zv * ph;
                if (m == 0) v = 0.f;
                C[(size_t)m * ldc + n] = v;
                __nv_bfloat16 hv, lv;
                split1(v, hv, lv);
                hhi[(size_t)m * LDX + n] = hv;
                hlo[(size_t)m * LDX + n] = lv;
            }
        }
    }
}

// ------------------ fp32 SIMT GEMM (discriminator only) --------------------
#define BM 64
#define BN 64
#define BKK 16
#define TMs 4
#define TNs 4

__global__ __launch_bounds__(256)
void disc_gemm(const float* __restrict__ A, int lda,
               const float* __restrict__ W, int ldw,
               int M, int N, int K,
               const float* __restrict__ bias,
               float* __restrict__ C, int ldc) {
    __shared__ float As[BKK][BM];
    __shared__ float Ws[BKK][BN];
    int bm = blockIdx.y * BM, bn = blockIdx.x * BN;
    int tid = threadIdx.x;
    int tr = tid >> 4, tc = tid & 15;
    float acc[TMs][TNs];
#pragma unroll
    for (int i = 0; i < TMs; i++)
#pragma unroll
        for (int j = 0; j < TNs; j++) acc[i][j] = 0.f;
    for (int k0 = 0; k0 < K; k0 += BKK) {
#pragma unroll
        for (int t = 0; t < 4; t++) {
            int l = tid + t * 256;
            int i = l >> 4, j = l & 15;
            int gm = bm + i, gk = k0 + j;
            As[j][i] = (gm < M && gk < K) ? A[(size_t)gm * lda + gk] : 0.f;
        }
#pragma unroll
        for (int t = 0; t < 4; t++) {
            int l = tid + t * 256;
            int i = l >> 4, j = l & 15;
            int gn = bn + i, gk = k0 + j;
            Ws[j][i] = (gn < N && gk < K) ? W[(size_t)gn * ldw + gk] : 0.f;
        }
        __syncthreads();
#pragma unroll
        for (int kk = 0; kk < BKK; kk++) {
            float a[TMs], w[TNs];
#pragma unroll
            for (int i = 0; i < TMs; i++) a[i] = As[kk][tr * TMs + i];
#pragma unroll
            for (int j = 0; j < TNs; j++) w[j] = Ws[kk][tc * TNs + j];
#pragma unroll
            for (int i = 0; i < TMs; i++)
#pragma unroll
                for (int j = 0; j < TNs; j++) acc[i][j] += a[i] * w[j];
        }
        __syncthreads();
    }
#pragma unroll
    for (int i = 0; i < TMs; i++) {
        int m = bm + tr * TMs + i;
        if (m >= M) continue;
#pragma unroll
        for (int j = 0; j < TNs; j++) {
            int n = bn + tc * TNs + j;
            if (n >= N) continue;
            float v = acc[i][j] + bias[n];
            v = (v > 0.f) ? v : 0.1f * v;
            C[(size_t)m * ldc + n] = v;
        }
    }
}

// ------------------------------- launcher ----------------------------------
extern "C" void kernel_launch(void* const* d_in, const int* in_sizes, int n_in,
                              void* d_out, int out_size) {
    const int*   fnode      = (const int*)d_in[0];
    const int*   fmess      = (const int*)d_in[1];
    const int*   node_graph = (const int*)d_in[2];
    const int*   mess_graph = (const int*)d_in[3];
    const int*   root_idx   = (const int*)d_in[4];
    const float* emb        = (const float*)d_in[5];
    const float* W_z_w      = (const float*)d_in[6];
    const float* W_z_b      = (const float*)d_in[7];
    const float* W_r_w      = (const float*)d_in[8];
    const float* U_r_w      = (const float*)d_in[9];
    const float* U_r_b      = (const float*)d_in[10];
    const float* W_h_w      = (const float*)d_in[11];
    const float* W_h_b      = (const float*)d_in[12];
    const float* D1_w       = (const float*)d_in[13];
    const float* D1_b       = (const float*)d_in[14];
    const float* D2_w       = (const float*)d_in[15];
    const float* D2_b       = (const float*)d_in[16];
    const float* D3_w       = (const float*)d_in[17];
    const float* D3_b       = (const float*)d_in[18];
    const int*   depthp     = (n_in > 19) ? (const int*)d_in[19] : nullptr;
    float*       out        = (float*)d_out;

    float *fe, *xzrh, *h, *hZU, *sumh, *z, *bias, *rv, *d1, *d2;
    __nv_bfloat16 *xhi, *xlo, *hhi, *hlo, *sghi, *sglo;
    __nv_bfloat16 *Wpre_hi, *Wpre_lo, *Wstep_hi, *Wstep_lo, *Whh_hi, *Whh_lo;
    cudaGetSymbolAddress((void**)&fe,       g_fe);
    cudaGetSymbolAddress((void**)&xzrh,     g_xzrh);
    cudaGetSymbolAddress((void**)&h,        g_h);
    cudaGetSymbolAddress((void**)&hZU,      g_hZU);
    cudaGetSymbolAddress((void**)&sumh,     g_sumh);
    cudaGetSymbolAddress((void**)&z,        g_z);
    cudaGetSymbolAddress((void**)&bias,     g_bias);
    cudaGetSymbolAddress((void**)&rv,       g_rv);
    cudaGetSymbolAddress((void**)&d1,       g_d1);
    cudaGetSymbolAddress((void**)&d2,       g_d2);
    cudaGetSymbolAddress((void**)&xhi,      g_xhi);
    cudaGetSymbolAddress((void**)&xlo,      g_xlo);
    cudaGetSymbolAddress((void**)&hhi,      g_hhi);
    cudaGetSymbolAddress((void**)&hlo,      g_hlo);
    cudaGetSymbolAddress((void**)&sghi,     g_sghi);
    cudaGetSymbolAddress((void**)&sglo,     g_sglo);
    cudaGetSymbolAddress((void**)&Wpre_hi,  g_Wpre_hi);
    cudaGetSymbolAddress((void**)&Wpre_lo,  g_Wpre_lo);
    cudaGetSymbolAddress((void**)&Wstep_hi, g_Wstep_hi);
    cudaGetSymbolAddress((void**)&Wstep_lo, g_Wstep_lo);
    cudaGetSymbolAddress((void**)&Whh_hi,   g_Whh_hi);
    cudaGetSymbolAddress((void**)&Whh_lo,   g_Whh_lo);

    cudaFuncSetAttribute(mma_gemm,
                         cudaFuncAttributeMaxDynamicSharedMemorySize, SMTOT);

    const int TPB = 256;

    // h = 0 (depth==0 path; overwritten when depth >= 1)
    zero_kernel<<<(MROWS * LDX + TPB - 1) / TPB, TPB>>>(h, MROWS * LDX);

    {
        int n = 1350 * HH + 900 * HH + HH * HH + 1350;
        pack_kernel<<<(n + TPB - 1) / TPB, TPB>>>(W_z_w, W_h_w, W_r_w, U_r_w,
                                                  W_z_b, W_h_b, U_r_b,
                                                  Wpre_hi, Wpre_lo,
                                                  Wstep_hi, Wstep_lo,
                                                  Whh_hi, Whh_lo, bias);
    }

    gather_fe_kernel<<<(NNODES * HH + TPB - 1) / TPB, TPB>>>(emb, fnode, fe);
    gather_x_kernel<<<(NMESS * HH + TPB - 1) / TPB, TPB>>>(fe, fmess, xhi, xlo);

    // xz|xh|xr = x @ Wpre^T  (N tiles: 11)
    mma_gemm<<<dim3(11, 47), 128, SMTOT>>>(xhi, xlo, Wpre_hi, Wpre_lo, 0,
        nullptr, nullptr, nullptr, nullptr, xzrh, LDPRE,
        nullptr, nullptr, nullptr, 0);

    step0_kernel<<<(NMESS * C2 + TPB - 1) / TPB, TPB>>>(xzrh, bias, h, hhi, hlo,
                                                        depthp);

    for (int s = 1; s < MAXDEPTH; s++) {
        mma_gemm<<<dim3(8, 47), 128, SMTOT>>>(hhi, hlo, Wstep_hi, Wstep_lo, 0,
            nullptr, nullptr, nullptr, nullptr, hZU, LDZU,
            nullptr, nullptr, depthp, s);
        step_gather_kernel<<<(NMESS * C2 + TPB - 1) / TPB, TPB>>>(
            h, hZU, xzrh, bias, mess_graph, sumh, z, sghi, sglo, depthp, s);
        // fused: h = mask*((1-z)*sumh + z*tanh(sumgh@Whh^T + xh + bh))
        mma_gemm<<<dim3(4, 47), 128, SMTOT>>>(sghi, sglo, Whh_hi, Whh_lo, 3,
            xzrh + HH, bias + HH, z, sumh, h, LDX,
            hhi, hlo, depthp, s);
    }

    readout_kernel<<<(BB * HH + TPB - 1) / TPB, TPB>>>(fe, h, root_idx, node_graph, rv);
    disc_gemm<<<dim3((DHH + BN - 1) / BN, (BB + BM - 1) / BM), 256>>>(
        rv, 2 * HH, D1_w, 2 * HH, BB, DHH, 2 * HH, D1_b, d1, DHH);
    disc_gemm<<<dim3((DHH + BN - 1) / BN, (BB + BM - 1) / BM), 256>>>(
        d1, DHH, D2_w, DHH, BB, DHH, DHH, D2_b, d2, DHH);
    score_kernel<<<(BB * 32 + TPB - 1) / TPB, TPB>>>(d2, D3_w, D3_b, out);
}

// round 12
// speedup vs baseline: 2.5681x; 1.0699x over previous
#include <cuda_runtime.h>
#include <cuda_bf16.h>
#include <cstdint>
#include <math.h>
#include <mma.h>

using namespace nvcuda;

// ---------------------------------------------------------------------------
// ScaffoldGAN JTNN GRU + discriminator. R12: bf16 HMMA GEMM, pre-split
// operands (R11) + 8-warp/64x32-warp-tile config (R8-style occupancy:
// acc=64 regs/thread -> 2 blocks/SM). Launch order shifted so ncu's
// "-s 5" lands on the first mma_gemm.
// ---------------------------------------------------------------------------

#define HH     450
#define NNODES 4000
#define NMESS  6000
#define KNB    6
#define BB     256
#define DHH    450
#define MAXDEPTH 15
#define MROWS  6016

#define LDX   512
#define LDZU  1024
#define LDPRE 1536

#define NTILE 15          // K = 480 = 15 x 32
#define KPADB 40          // bf16 elems per smem row (80 B)
#define STG   10240       // one operand stage: 128*KPADB*2 B
#define SMTOT 81920       // 2 stages x 4 operands

// ---------------- device scratch (zero-initialized; pads never written) ----
__device__ float g_fe[NNODES * HH];
__device__ float g_xzrh[MROWS * LDPRE];
__device__ float g_h[MROWS * LDX];
__device__ float g_hZU[MROWS * LDZU];
__device__ float g_sumh[MROWS * LDX];
__device__ float g_z[MROWS * LDX];
__device__ float g_bias[1536];
__device__ float g_rv[BB * 2 * HH];
__device__ float g_d1[BB * DHH];
__device__ float g_d2[BB * DHH];
__device__ __nv_bfloat16 g_xhi[MROWS * LDX];
__device__ __nv_bfloat16 g_xlo[MROWS * LDX];
__device__ __nv_bfloat16 g_hhi[MROWS * LDX];
__device__ __nv_bfloat16 g_hlo[MROWS * LDX];
__device__ __nv_bfloat16 g_sghi[MROWS * LDX];
__device__ __nv_bfloat16 g_sglo[MROWS * LDX];
__device__ __nv_bfloat16 g_Wpre_hi[1408 * LDX];
__device__ __nv_bfloat16 g_Wpre_lo[1408 * LDX];
__device__ __nv_bfloat16 g_Wstep_hi[1024 * LDX];
__device__ __nv_bfloat16 g_Wstep_lo[1024 * LDX];
__device__ __nv_bfloat16 g_Whh_hi[512 * LDX];
__device__ __nv_bfloat16 g_Whh_lo[512 * LDX];

// --------------------------- helpers ---------------------------------------
__device__ __forceinline__ uint32_t smem_u32(const void* p) {
    uint32_t a;
    asm("{ .reg .u64 t; cvta.to.shared.u64 t, %1; cvt.u32.u64 %0, t; }"
        : "=r"(a) : "l"(p));
    return a;
}
#define CP16(d, s) \
    asm volatile("cp.async.cg.shared.global [%0], [%1], 16;" \
                 :: "r"(d), "l"(s) : "memory")
#define CP_COMMIT asm volatile("cp.async.commit_group;" ::: "memory")
#define CP_WAIT1  asm volatile("cp.async.wait_group 1;" ::: "memory")
#define CP_WAIT0  asm volatile("cp.async.wait_group 0;" ::: "memory")

__device__ __forceinline__ void split1(float v, __nv_bfloat16& hi, __nv_bfloat16& lo) {
    hi = __float2bfloat16(v);
    lo = __float2bfloat16(v - __bfloat162float(hi));
}
__device__ __forceinline__ float2 sigm2(float2 v) {
    return make_float2(1.f / (1.f + __expf(-v.x)), 1.f / (1.f + __expf(-v.y)));
}
__device__ __forceinline__ float2 tanh2(float2 v) {
    return make_float2(tanhf(v.x), tanhf(v.y));
}

// ---------------------------- small kernels --------------------------------
__global__ void zero_kernel(float* p, int n) {
    int i = blockIdx.x * blockDim.x + threadIdx.x;
    if (i < n) p[i] = 0.f;
}

__global__ void pack_kernel(const float* __restrict__ W_z_w,
                            const float* __restrict__ W_h_w,
                            const float* __restrict__ W_r_w,
                            const float* __restrict__ U_r_w,
                            const float* __restrict__ W_z_b,
                            const float* __restrict__ W_h_b,
                            const float* __restrict__ U_r_b,
                            __nv_bfloat16* __restrict__ Wpre_hi,
                            __nv_bfloat16* __restrict__ Wpre_lo,
                            __nv_bfloat16* __restrict__ Wstep_hi,
                            __nv_bfloat16* __restrict__ Wstep_lo,
                            __nv_bfloat16* __restrict__ Whh_hi,
                            __nv_bfloat16* __restrict__ Whh_lo,
                            float* __restrict__ bias) {
    int i = blockIdx.x * blockDim.x + threadIdx.x;
    const int NPRE  = 1350 * HH;
    const int NSTEP = 900 * HH;
    const int NWHH  = HH * HH;
    if (i < NPRE) {
        int n = i / HH, k = i - n * HH;
        float v;
        if (n < HH)            v = W_z_w[n * 2 * HH + k];
        else if (n < 2 * HH)   v = W_h_w[(n - HH) * 2 * HH + k];
        else                   v = W_r_w[(n - 2 * HH) * HH + k];
        split1(v, Wpre_hi[n * LDX + k], Wpre_lo[n * LDX + k]);
    } else if (i < NPRE + NSTEP) {
        int j = i - NPRE;
        int n = j / HH, k = j - n * HH;
        float v = (n < HH) ? W_z_w[n * 2 * HH + HH + k]
                           : U_r_w[(n - HH) * HH + k];
        split1(v, Wstep_hi[n * LDX + k], Wstep_lo[n * LDX + k]);
    } else if (i < NPRE + NSTEP + NWHH) {
        int j = i - NPRE - NSTEP;
        int n = j / HH, k = j - n * HH;
        float v = W_h_w[n * 2 * HH + HH + k];
        split1(v, Whh_hi[n * LDX + k], Whh_lo[n * LDX + k]);
    } else if (i < NPRE + NSTEP + NWHH + 1350) {
        int n = i - NPRE - NSTEP - NWHH;
        bias[n] = (n < HH) ? W_z_b[n]
                : (n < 2 * HH) ? W_h_b[n - HH]
                : U_r_b[n - 2 * HH];
    }
}

__global__ void gather_fe_kernel(const float* __restrict__ emb,
                                 const int* __restrict__ fnode,
                                 float* __restrict__ fe) {
    int i = blockIdx.x * blockDim.x + threadIdx.x;
    if (i >= NNODES * HH) return;
    int r = i / HH, c = i - r * HH;
    fe[i] = emb[fnode[r] * HH + c];
}

__global__ void gather_x_kernel(const float* __restrict__ fe,
                                const int* __restrict__ fmess,
                                __nv_bfloat16* __restrict__ xhi,
                                __nv_bfloat16* __restrict__ xlo) {
    int i = blockIdx.x * blockDim.x + threadIdx.x;
    if (i >= NMESS * HH) return;
    int r = i / HH, c = i - r * HH;
    float v = fe[fmess[r] * HH + c];
    split1(v, xhi[(size_t)r * LDX + c], xlo[(size_t)r * LDX + c]);
}

#define C2 225

__global__ void step0_kernel(const float* __restrict__ xzrh,
                             const float* __restrict__ bias,
                             float* __restrict__ h,
                             __nv_bfloat16* __restrict__ hhi,
                             __nv_bfloat16* __restrict__ hlo,
                             const int* __restrict__ depthp) {
    if (depthp && __ldg(depthp) < 1) return;
    int i = blockIdx.x * blockDim.x + threadIdx.x;
    if (i >= NMESS * C2) return;
    int m = i / C2, c = i - m * C2;
    const float2* xp = (const float2*)xzrh + (size_t)m * (LDPRE / 2);
    const float2* bp = (const float2*)bias;
    float2 xz = xp[c],        bz = bp[c];
    float2 xh = xp[C2 + c],   bh = bp[C2 + c];
    float2 zv = sigm2(make_float2(xz.x + bz.x, xz.y + bz.y));
    float2 ph = tanh2(make_float2(xh.x + bh.x, xh.y + bh.y));
    float2 v = make_float2(zv.x * ph.x, zv.y * ph.y);
    if (m == 0) v = make_float2(0.f, 0.f);
    size_t o = (size_t)m * (LDX / 2) + c;
    ((float2*)h)[o] = v;
    __nv_bfloat162 hi2, lo2;
    split1(v.x, hi2.x, lo2.x);
    split1(v.y, hi2.y, lo2.y);
    ((__nv_bfloat162*)hhi)[o] = hi2;
    ((__nv_bfloat162*)hlo)[o] = lo2;
}

__global__ void step_gather_kernel(const float* __restrict__ h,
                                   const float* __restrict__ hZU,
                                   const float* __restrict__ xzrh,
                                   const float* __restrict__ bias,
                                   const int* __restrict__ mg,
                                   float* __restrict__ sumh,
                                   float* __restrict__ z,
                                   __nv_bfloat16* __restrict__ sghi,
                                   __nv_bfloat16* __restrict__ sglo,
                                   const int* __restrict__ depthp, int step) {
    if (depthp && step >= __ldg(depthp)) return;
    int i = blockIdx.x * blockDim.x + threadIdx.x;
    if (i >= NMESS * C2) return;
    int m = i / C2, c = i - m * C2;
    const float2* xp = (const float2*)xzrh + (size_t)m * (LDPRE / 2);
    const float2* bp = (const float2*)bias;
    float2 xr = xp[2 * C2 + c], br = bp[2 * C2 + c];
    float xr0 = xr.x + br.x, xr1 = xr.y + br.y;
    float2 sh = make_float2(0.f, 0.f);
    float2 sz = make_float2(0.f, 0.f);
    float2 sg = make_float2(0.f, 0.f);
    int idx[KNB];
#pragma unroll
    for (int k = 0; k < KNB; k++) idx[k] = mg[m * KNB + k];
#pragma unroll
    for (int k = 0; k < KNB; k++) {
        int j = idx[k];
        float2 hv = ((const float2*)h)[(size_t)j * (LDX / 2) + c];
        float2 zz = ((const float2*)hZU)[(size_t)j * (LDZU / 2) + c];
        float2 uu = ((const float2*)hZU)[(size_t)j * (LDZU / 2) + C2 + c];
        sh.x += hv.x; sh.y += hv.y;
        sz.x += zz.x; sz.y += zz.y;
        sg.x += hv.x / (1.f + __expf(-(xr0 + uu.x)));
        sg.y += hv.y / (1.f + __expf(-(xr1 + uu.y)));
    }
    size_t o = (size_t)m * (LDX / 2) + c;
    ((float2*)sumh)[o] = sh;
    float2 xz = xp[c], bz = bp[c];
    ((float2*)z)[o] = sigm2(make_float2(sz.x + xz.x + bz.x, sz.y + xz.y + bz.y));
    __nv_bfloat162 hi2, lo2;
    split1(sg.x, hi2.x, lo2.x);
    split1(sg.y, hi2.y, lo2.y);
    ((__nv_bfloat162*)sghi)[o] = hi2;
    ((__nv_bfloat162*)sglo)[o] = lo2;
}

__global__ void readout_kernel(const float* __restrict__ fe,
                               const float* __restrict__ h,
                               const int* __restrict__ root,
                               const int* __restrict__ ng,
                               float* __restrict__ rv) {
    int i = blockIdx.x * blockDim.x + threadIdx.x;
    if (i >= BB * HH) return;
    int b = i / HH, c = i - b * HH;
    int node = root[b];
    rv[b * 2 * HH + c] = fe[node * HH + c];
    float s = 0.f;
#pragma unroll
    for (int k = 0; k < KNB; k++)
        s += h[(size_t)ng[node * KNB + k] * LDX + c];
    rv[b * 2 * HH + HH + c] = s;
}

__global__ void score_kernel(const float* __restrict__ h2,
                             const float* __restrict__ w,
                             const float* __restrict__ b3,
                             float* __restrict__ out) {
    int gt = blockIdx.x * blockDim.x + threadIdx.x;
    int warp = gt >> 5, lane = gt & 31;
    if (warp >= BB) return;
    float s = 0.f;
    for (int k = lane; k < DHH; k += 32) s += h2[warp * DHH + k] * w[k];
#pragma unroll
    for (int o = 16; o; o >>= 1) s += __shfl_xor_sync(0xffffffffu, s, o);
    if (lane == 0) out[warp] = s + b3[0];
}

// ----------------- bf16 HMMA GEMM, pre-split operands ----------------------
// acc = Alo@Bhi^T + Ahi@Blo^T + Ahi@Bhi^T over K=480. 256 threads, 8 warps,
// 64x32 warp tiles (2M x 4N). mode 0: C = acc. mode 3: fused GRU h-update.
__global__ __launch_bounds__(256)
void mma_gemm(const __nv_bfloat16* __restrict__ Ah,
              const __nv_bfloat16* __restrict__ Al,
              const __nv_bfloat16* __restrict__ Bh,
              const __nv_bfloat16* __restrict__ Bl,
              int mode,
              const float* __restrict__ pre,
              const float* __restrict__ biasp,
              const float* __restrict__ z,
              const float* __restrict__ sumh,
              float* __restrict__ C, int ldc,
              __nv_bfloat16* __restrict__ hhi,
              __nv_bfloat16* __restrict__ hlo,
              const int* __restrict__ depthp, int step) {
    if (depthp && step >= __ldg(depthp)) return;

    extern __shared__ __align__(16) char smem[];
    const uint32_t sb = smem_u32(smem);
    const int tid = threadIdx.x;
    const int warp = tid >> 5;
    const int wm = warp & 1;    // 2 x 64-row halves
    const int wn = warp >> 1;   // 4 x 32-col quarters
    const int bm = blockIdx.y * 128;
    const int bn = blockIdx.x * 128;

    wmma::fragment<wmma::accumulator, 16, 16, 16, float> acc[4][2];
#pragma unroll
    for (int i = 0; i < 4; i++)
#pragma unroll
        for (int j = 0; j < 2; j++) wmma::fill_fragment(acc[i][j], 0.f);

    // loader: per stage 4 operands x 512 x16B chunks; 256 thr x 2 per operand
    auto load_stage = [&](int stg, int kc) {
        uint32_t base = sb + (uint32_t)stg * 4 * STG;
#pragma unroll
        for (int t = 0; t < 2; t++) {
            int u = tid + t * 256;
            int row = u >> 2, q = u & 3;
            uint32_t so = (uint32_t)(row * KPADB + q * 8) * 2;
            size_t ao = (size_t)(bm + row) * LDX + kc + q * 8;
            size_t bo = (size_t)(bn + row) * LDX + kc + q * 8;
            CP16(base + so,            Ah + ao);
            CP16(base + STG + so,      Al + ao);
            CP16(base + 2 * STG + so,  Bh + bo);
            CP16(base + 3 * STG + so,  Bl + bo);
        }
    };

    auto do_mma = [&](int stg) {
        const __nv_bfloat16* SAh = (const __nv_bfloat16*)(smem + (size_t)stg * 4 * STG);
        const __nv_bfloat16* SAl = (const __nv_bfloat16*)(smem + (size_t)stg * 4 * STG + STG);
        const __nv_bfloat16* SBh = (const __nv_bfloat16*)(smem + (size_t)stg * 4 * STG + 2 * STG);
        const __nv_bfloat16* SBl = (const __nv_bfloat16*)(smem + (size_t)stg * 4 * STG + 3 * STG);
#pragma unroll
        for (int kk = 0; kk < 32; kk += 16) {
            wmma::fragment<wmma::matrix_b, 16, 16, 16, __nv_bfloat16,
                           wmma::col_major> bhi[2], blo[2];
#pragma unroll
            for (int j = 0; j < 2; j++) {
                wmma::load_matrix_sync(bhi[j], SBh + (wn * 32 + j * 16) * KPADB + kk, KPADB);
                wmma::load_matrix_sync(blo[j], SBl + (wn * 32 + j * 16) * KPADB + kk, KPADB);
            }
#pragma unroll
            for (int i = 0; i < 4; i++) {
                wmma::fragment<wmma::matrix_a, 16, 16, 16, __nv_bfloat16,
                               wmma::row_major> ahi, alo;
                wmma::load_matrix_sync(ahi, SAh + (wm * 64 + i * 16) * KPADB + kk, KPADB);
                wmma::load_matrix_sync(alo, SAl + (wm * 64 + i * 16) * KPADB + kk, KPADB);
#pragma unroll
                for (int j = 0; j < 2; j++) {
                    wmma::mma_sync(acc[i][j], alo, bhi[j], acc[i][j]);
                    wmma::mma_sync(acc[i][j], ahi, blo[j], acc[i][j]);
                    wmma::mma_sync(acc[i][j], ahi, bhi[j], acc[i][j]);
                }
            }
        }
    };

    load_stage(0, 0);
    CP_COMMIT;
    for (int ch = 0; ch < NTILE; ch++) {
        if (ch + 1 < NTILE) {
            load_stage((ch + 1) & 1, (ch + 1) * 32);
            CP_COMMIT;
            CP_WAIT1;
        } else {
            CP_WAIT0;
        }
        __syncthreads();
        do_mma(ch & 1);
        __syncthreads();
    }

    if (mode == 0) {
#pragma unroll
        for (int i = 0; i < 4; i++)
#pragma unroll
            for (int j = 0; j < 2; j++) {
                float* cp = C + (size_t)(bm + wm * 64 + i * 16) * ldc
                              + bn + wn * 32 + j * 16;
                wmma::store_matrix_sync(cp, acc[i][j], ldc, wmma::mem_row_major);
            }
    } else {
        float* Cs = (float*)smem;
#pragma unroll
        for (int i = 0; i < 4; i++)
#pragma unroll
            for (int j = 0; j < 2; j++) {
                float* cp = Cs + (size_t)(wm * 64 + i * 16) * 132
                               + wn * 32 + j * 16;
                wmma::store_matrix_sync(cp, acc[i][j], 132, wmma::mem_row_major);
            }
        __syncthreads();
        int n = bn + (tid & 127);
        int half = tid >> 7;
        if (n < HH) {
            for (int r = 0; r < 64; r++) {
                int row = half * 64 + r;
                int m = bm + row;
                float accv = Cs[(size_t)row * 132 + (tid & 127)];
                float ph = tanhf(accv + pre[(size_t)m * LDPRE + n] + biasp[n]);
                float zv = z[(size_t)m * LDX + n];
                float sh = sumh[(size_t)m * LDX + n];
                float v = (1.f - zv) * sh + zv * ph;
                if (m == 0) v = 0.f;
                C[(size_t)m * ldc + n] = v;
                __nv_bfloat16 hv, lv;
                split1(v, hv, lv);
                hhi[(size_t)m * LDX + n] = hv;
                hlo[(size_t)m * LDX + n] = lv;
            }
        }
    }
}

// ------------------ fp32 SIMT GEMM (discriminator only) --------------------
#define BM 64
#define BN 64
#define BKK 16
#define TMs 4
#define TNs 4

__global__ __launch_bounds__(256)
void disc_gemm(const float* __restrict__ A, int lda,
               const float* __restrict__ W, int ldw,
               int M, int N, int K,
               const float* __restrict__ bias,
               float* __restrict__ C, int ldc) {
    __shared__ float As[BKK][BM];
    __shared__ float Ws[BKK][BN];
    int bm = blockIdx.y * BM, bn = blockIdx.x * BN;
    int tid = threadIdx.x;
    int tr = tid >> 4, tc = tid & 15;
    float acc[TMs][TNs];
#pragma unroll
    for (int i = 0; i < TMs; i++)
#pragma unroll
        for (int j = 0; j < TNs; j++) acc[i][j] = 0.f;
    for (int k0 = 0; k0 < K; k0 += BKK) {
#pragma unroll
        for (int t = 0; t < 4; t++) {
            int l = tid + t * 256;
            int i = l >> 4, j = l & 15;
            int gm = bm + i, gk = k0 + j;
            As[j][i] = (gm < M && gk < K) ? A[(size_t)gm * lda + gk] : 0.f;
        }
#pragma unroll
        for (int t = 0; t < 4; t++) {
            int l = tid + t * 256;
            int i = l >> 4, j = l & 15;
            int gn = bn + i, gk = k0 + j;
            Ws[j][i] = (gn < N && gk < K) ? W[(size_t)gn * ldw + gk] : 0.f;
        }
        __syncthreads();
#pragma unroll
        for (int kk = 0; kk < BKK; kk++) {
            float a[TMs], w[TNs];
#pragma unroll
            for (int i = 0; i < TMs; i++) a[i] = As[kk][tr * TMs + i];
#pragma unroll
            for (int j = 0; j < TNs; j++) w[j] = Ws[kk][tc * TNs + j];
#pragma unroll
            for (int i = 0; i < TMs; i++)
#pragma unroll
                for (int j = 0; j < TNs; j++) acc[i][j] += a[i] * w[j];
        }
        __syncthreads();
    }
#pragma unroll
    for (int i = 0; i < TMs; i++) {
        int m = bm + tr * TMs + i;
        if (m >= M) continue;
#pragma unroll
        for (int j = 0; j < TNs; j++) {
            int n = bn + tc * TNs + j;
            if (n >= N) continue;
            float v = acc[i][j] + bias[n];
            v = (v > 0.f) ? v : 0.1f * v;
            C[(size_t)m * ldc + n] = v;
        }
    }
}

// ------------------------------- launcher ----------------------------------
extern "C" void kernel_launch(void* const* d_in, const int* in_sizes, int n_in,
                              void* d_out, int out_size) {
    const int*   fnode      = (const int*)d_in[0];
    const int*   fmess      = (const int*)d_in[1];
    const int*   node_graph = (const int*)d_in[2];
    const int*   mess_graph = (const int*)d_in[3];
    const int*   root_idx   = (const int*)d_in[4];
    const float* emb        = (const float*)d_in[5];
    const float* W_z_w      = (const float*)d_in[6];
    const float* W_z_b      = (const float*)d_in[7];
    const float* W_r_w      = (const float*)d_in[8];
    const float* U_r_w      = (const float*)d_in[9];
    const float* U_r_b      = (const float*)d_in[10];
    const float* W_h_w      = (const float*)d_in[11];
    const float* W_h_b      = (const float*)d_in[12];
    const float* D1_w       = (const float*)d_in[13];
    const float* D1_b       = (const float*)d_in[14];
    const float* D2_w       = (const float*)d_in[15];
    const float* D2_b       = (const float*)d_in[16];
    const float* D3_w       = (const float*)d_in[17];
    const float* D3_b       = (const float*)d_in[18];
    const int*   depthp     = (n_in > 19) ? (const int*)d_in[19] : nullptr;
    float*       out        = (float*)d_out;

    float *fe, *xzrh, *h, *hZU, *sumh, *z, *bias, *rv, *d1, *d2;
    __nv_bfloat16 *xhi, *xlo, *hhi, *hlo, *sghi, *sglo;
    __nv_bfloat16 *Wpre_hi, *Wpre_lo, *Wstep_hi, *Wstep_lo, *Whh_hi, *Whh_lo;
    cudaGetSymbolAddress((void**)&fe,       g_fe);
    cudaGetSymbolAddress((void**)&xzrh,     g_xzrh);
    cudaGetSymbolAddress((void**)&h,        g_h);
    cudaGetSymbolAddress((void**)&hZU,      g_hZU);
    cudaGetSymbolAddress((void**)&sumh,     g_sumh);
    cudaGetSymbolAddress((void**)&z,        g_z);
    cudaGetSymbolAddress((void**)&bias,     g_bias);
    cudaGetSymbolAddress((void**)&rv,       g_rv);
    cudaGetSymbolAddress((void**)&d1,       g_d1);
    cudaGetSymbolAddress((void**)&d2,       g_d2);
    cudaGetSymbolAddress((void**)&xhi,      g_xhi);
    cudaGetSymbolAddress((void**)&xlo,      g_xlo);
    cudaGetSymbolAddress((void**)&hhi,      g_hhi);
    cudaGetSymbolAddress((void**)&hlo,      g_hlo);
    cudaGetSymbolAddress((void**)&sghi,     g_sghi);
    cudaGetSymbolAddress((void**)&sglo,     g_sglo);
    cudaGetSymbolAddress((void**)&Wpre_hi,  g_Wpre_hi);
    cudaGetSymbolAddress((void**)&Wpre_lo,  g_Wpre_lo);
    cudaGetSymbolAddress((void**)&Wstep_hi, g_Wstep_hi);
    cudaGetSymbolAddress((void**)&Wstep_lo, g_Wstep_lo);
    cudaGetSymbolAddress((void**)&Whh_hi,   g_Whh_hi);
    cudaGetSymbolAddress((void**)&Whh_lo,   g_Whh_lo);

    cudaFuncSetAttribute(mma_gemm,
                         cudaFuncAttributeMaxDynamicSharedMemorySize, SMTOT);

    const int TPB = 256;

    // launches 0,1: h = 0 split in two (shifts first mma_gemm to launch #5
    // so ncu "-s 5 -c 1" profiles the GEMM)
    const int HHALF = (MROWS * LDX) / 2;
    zero_kernel<<<(HHALF + TPB - 1) / TPB, TPB>>>(h, HHALF);
    zero_kernel<<<(HHALF + TPB - 1) / TPB, TPB>>>(h + HHALF, MROWS * LDX - HHALF);

    {   // launch 2
        int n = 1350 * HH + 900 * HH + HH * HH + 1350;
        pack_kernel<<<(n + TPB - 1) / TPB, TPB>>>(W_z_w, W_h_w, W_r_w, U_r_w,
                                                  W_z_b, W_h_b, U_r_b,
                                                  Wpre_hi, Wpre_lo,
                                                  Wstep_hi, Wstep_lo,
                                                  Whh_hi, Whh_lo, bias);
    }

    // launches 3,4
    gather_fe_kernel<<<(NNODES * HH + TPB - 1) / TPB, TPB>>>(emb, fnode, fe);
    gather_x_kernel<<<(NMESS * HH + TPB - 1) / TPB, TPB>>>(fe, fmess, xhi, xlo);

    // launch 5: profiled GEMM
    mma_gemm<<<dim3(11, 47), 256, SMTOT>>>(xhi, xlo, Wpre_hi, Wpre_lo, 0,
        nullptr, nullptr, nullptr, nullptr, xzrh, LDPRE,
        nullptr, nullptr, nullptr, 0);

    step0_kernel<<<(NMESS * C2 + TPB - 1) / TPB, TPB>>>(xzrh, bias, h, hhi, hlo,
                                                        depthp);

    for (int s = 1; s < MAXDEPTH; s++) {
        mma_gemm<<<dim3(8, 47), 256, SMTOT>>>(hhi, hlo, Wstep_hi, Wstep_lo, 0,
            nullptr, nullptr, nullptr, nullptr, hZU, LDZU,
            nullptr, nullptr, depthp, s);
        step_gather_kernel<<<(NMESS * C2 + TPB - 1) / TPB, TPB>>>(
            h, hZU, xzrh, bias, mess_graph, sumh, z, sghi, sglo, depthp, s);
        mma_gemm<<<dim3(4, 47), 256, SMTOT>>>(sghi, sglo, Whh_hi, Whh_lo, 3,
            xzrh + HH, bias + HH, z, sumh, h, LDX,
            hhi, hlo, depthp, s);
    }

    readout_kernel<<<(BB * HH + TPB - 1) / TPB, TPB>>>(fe, h, root_idx, node_graph, rv);
    disc_gemm<<<dim3((DHH + BN - 1) / BN, (BB + BM - 1) / BM), 256>>>(
        rv, 2 * HH, D1_w, 2 * HH, BB, DHH, 2 * HH, D1_b, d1, DHH);
    disc_gemm<<<dim3((DHH + BN - 1) / BN, (BB + BM - 1) / BM), 256>>>(
        d1, DHH, D2_w, DHH, BB, DHH, DHH, D2_b, d2, DHH);
    score_kernel<<<(BB * 32 + TPB - 1) / TPB, TPB>>>(d2, D3_w, D3_b, out);
}